// round 9
// baseline (speedup 1.0000x reference)
#include <cuda_runtime.h>
#include <cuda_bf16.h>
#include <cstdint>
#include <math.h>

#define NL    4
#define BATCH 2
#define SEQ   1024
#define DM    1024
#define DI    2048
#define DTR   64
#define NS    16
#define DC    4
#define MTOT  (BATCH*SEQ)   // 2048
#define KSPLIT 8

typedef __nv_bfloat16 bf16;

// ---------------- scratch (device globals; no allocation allowed) ----------
__device__ float g_x  [MTOT*DM];
__device__ float g_xz [MTOT*2*DI];
__device__ float g_xm [MTOT*DI];
__device__ float g_dbcp[KSPLIT*MTOT*96];
__device__ float g_dbc[MTOT*96];
__device__ float g_dt [MTOT*DI];

__device__ __align__(128) bf16 g_lnh[MTOT*DM];
__device__ __align__(128) bf16 g_xmh[MTOT*DI];
__device__ __align__(128) bf16 g_xml[MTOT*DI];
__device__ __align__(128) bf16 g_dbch[MTOT*96];
__device__ __align__(128) bf16 g_dbcl[MTOT*96];
__device__ __align__(128) bf16 g_yh [MTOT*DI];
__device__ __align__(128) bf16 w_inh [NL*2*DI*DM];
__device__ __align__(128) bf16 w_xph [NL*96*DI];
__device__ __align__(128) bf16 w_xpl [NL*96*DI];
__device__ __align__(128) bf16 w_dth [NL*DI*DTR];
__device__ __align__(128) bf16 w_dtl [NL*DI*DTR];
__device__ __align__(128) bf16 w_outh[NL*DM*DI];

// ---------------- helpers --------------------------------------------------
__device__ __forceinline__ uint32_t smem_u32(const void* p) {
    uint32_t a;
    asm("{ .reg .u64 t; cvta.to.shared.u64 t, %1; cvt.u32.u64 %0, t; }"
        : "=r"(a) : "l"(p));
    return a;
}
#define SW64(x) ((x) ^ (((x) >> 3) & 0x30))

__device__ __forceinline__ void cp16(uint32_t dst, const void* src, int sz) {
    asm volatile("cp.async.cg.shared.global [%0], [%1], 16, %2;"
                 :: "r"(dst), "l"(src), "r"(sz) : "memory");
}
#define CP_COMMIT() asm volatile("cp.async.commit_group;" ::: "memory")
#define CP_WAIT(n)  asm volatile("cp.async.wait_group %0;" :: "n"(n) : "memory")

__device__ __forceinline__ void ldsm4(uint32_t* d, uint32_t addr) {
    asm volatile("ldmatrix.sync.aligned.m8n8.x4.shared.b16 {%0,%1,%2,%3}, [%4];"
        : "=r"(d[0]), "=r"(d[1]), "=r"(d[2]), "=r"(d[3]) : "r"(addr));
}
__device__ __forceinline__ void mma16816(float* c, const uint32_t* a,
                                         uint32_t b0, uint32_t b1) {
    asm volatile(
        "mma.sync.aligned.m16n8k16.row.col.f32.bf16.bf16.f32 "
        "{%0,%1,%2,%3}, {%4,%5,%6,%7}, {%8,%9}, {%0,%1,%2,%3};"
        : "+f"(c[0]), "+f"(c[1]), "+f"(c[2]), "+f"(c[3])
        : "r"(a[0]), "r"(a[1]), "r"(a[2]), "r"(a[3]), "r"(b0), "r"(b1));
}

__device__ __forceinline__ float softplusf(float v) {
    return (v > 20.f) ? v : log1pf(__expf(v));
}
__device__ __forceinline__ void split_bf16(float v, bf16* hp, bf16* lp) {
    bf16 h = __float2bfloat16(v);
    *hp = h;
    *lp = __float2bfloat16(v - __bfloat162float(h));
}

// ---------------- misc kernels --------------------------------------------
__global__ void copy_kernel(const float* __restrict__ a, float* __restrict__ o, int n) {
    int i = blockIdx.x * 256 + threadIdx.x;
    if (i < n) o[i] = a[i];
}
// vectorized hi-only convert: 8 elems/thread
__global__ void cvt_hi(const float* __restrict__ src, bf16* __restrict__ hi, int n8) {
    int i = blockIdx.x * 256 + threadIdx.x;
    if (i >= n8) return;
    const float4* s = (const float4*)(src + (size_t)i * 8);
    float4 a = s[0], b = s[1];
    bf16 t[8];
    t[0]=__float2bfloat16(a.x); t[1]=__float2bfloat16(a.y);
    t[2]=__float2bfloat16(a.z); t[3]=__float2bfloat16(a.w);
    t[4]=__float2bfloat16(b.x); t[5]=__float2bfloat16(b.y);
    t[6]=__float2bfloat16(b.z); t[7]=__float2bfloat16(b.w);
    *(uint4*)(hi + (size_t)i * 8) = *(uint4*)t;
}
// vectorized hi/lo split convert: 8 elems/thread
__global__ void cvt_split(const float* __restrict__ src, bf16* __restrict__ hi,
                          bf16* __restrict__ lo, int n8) {
    int i = blockIdx.x * 256 + threadIdx.x;
    if (i >= n8) return;
    const float4* s = (const float4*)(src + (size_t)i * 8);
    float4 a = s[0], b = s[1];
    float v[8] = {a.x, a.y, a.z, a.w, b.x, b.y, b.z, b.w};
    bf16 th[8], tl[8];
#pragma unroll
    for (int j = 0; j < 8; j++) {
        bf16 h = __float2bfloat16(v[j]);
        th[j] = h;
        tl[j] = __float2bfloat16(v[j] - __bfloat162float(h));
    }
    *(uint4*)(hi + (size_t)i * 8) = *(uint4*)th;
    *(uint4*)(lo + (size_t)i * 8) = *(uint4*)tl;
}

// ---------------- layernorm (float4 rows) ----------------------------------
// BF=1: write bf16 hi only; BF=0: write fp32
template<int BF>
__global__ __launch_bounds__(256)
void ln_kernel(const float* __restrict__ in, float* __restrict__ outp,
               bf16* __restrict__ oh,
               const float* __restrict__ gw, const float* __restrict__ bw)
{
    int row = blockIdx.x;
    int t = threadIdx.x;
    float4 v = ((const float4*)(in + (size_t)row * DM))[t];
    float s  = v.x + v.y + v.z + v.w;
    float s2 = v.x*v.x + v.y*v.y + v.z*v.z + v.w*v.w;
#pragma unroll
    for (int o = 16; o > 0; o >>= 1) {
        s  += __shfl_xor_sync(0xffffffffu, s,  o);
        s2 += __shfl_xor_sync(0xffffffffu, s2, o);
    }
    __shared__ float sh[16];
    if ((t & 31) == 0) { sh[t >> 5] = s; sh[(t >> 5) + 8] = s2; }
    __syncthreads();
    float S = 0.f, S2 = 0.f;
#pragma unroll
    for (int i = 0; i < 8; i++) { S += sh[i]; S2 += sh[i + 8]; }
    float mu  = S * (1.f / DM);
    float var = S2 * (1.f / DM) - mu * mu;
    float r   = rsqrtf(var + 1e-5f);
    float4 g = ((const float4*)gw)[t];
    float4 b = ((const float4*)bw)[t];
    float4 o4;
    o4.x = (v.x - mu) * r * g.x + b.x;
    o4.y = (v.y - mu) * r * g.y + b.y;
    o4.z = (v.z - mu) * r * g.z + b.z;
    o4.w = (v.w - mu) * r * g.w + b.w;
    if (BF) {
        bf16 t4[4] = {__float2bfloat16(o4.x), __float2bfloat16(o4.y),
                      __float2bfloat16(o4.z), __float2bfloat16(o4.w)};
        *(uint2*)(oh + (size_t)row * DM + t * 4) = *(uint2*)t4;
    } else {
        ((float4*)(outp + (size_t)row * DM))[t] = o4;
    }
}

// ---------------- causal depthwise conv (k=4) + SiLU + bf16 split ---------
__global__ __launch_bounds__(256)
void conv_silu(const float* __restrict__ xz, const float* __restrict__ cw,
               const float* __restrict__ cb, float* __restrict__ xmout,
               bf16* __restrict__ oh, bf16* __restrict__ ol)
{
    int d = blockIdx.x * 256 + threadIdx.x;
    int l = blockIdx.y;
    int b = blockIdx.z;
    float acc = cb[d];
#pragma unroll
    for (int j = 0; j < DC; j++) {
        int lj = l - (DC - 1) + j;
        if (lj >= 0)
            acc = fmaf(cw[d * DC + j], xz[(size_t)(b * SEQ + lj) * (2 * DI) + d], acc);
    }
    float sv = acc / (1.f + __expf(-acc));
    size_t o = (size_t)(b * SEQ + l) * DI + d;
    xmout[o] = sv;
    split_bf16(sv, oh + o, ol + o);
}

// ---------------- reduce split-K partials + bf16 split --------------------
__global__ void reduce8(const float* __restrict__ part, float* __restrict__ outp,
                        bf16* __restrict__ oh, bf16* __restrict__ ol)
{
    int i = blockIdx.x * 256 + threadIdx.x;
    float s = 0.f;
#pragma unroll
    for (int k = 0; k < KSPLIT; k++) s += part[(size_t)k * (MTOT * 96) + i];
    outp[i] = s;
    split_bf16(s, oh + i, ol + i);
}

// ---------------- bf16 GEMM, cp.async double-buffered ----------------------
// TERMS=1: C = Ah*Bh^T (plain bf16).  TERMS=3: 3-term split ah*bh+ah*bl+al*bh.
// Block 128x128, 8 warps (2m x 4n), warp tile 64x32. BK=32, 2 smem stages.
// EPI: 0 = store, 1 = C += acc, 2 = softplus(acc + bias[n])
// gridDim.z > 1 => split-K: z handles K-chunk [z*K,(z+1)*K), writes C + z*M*N.
template<int EPI, int TERMS>
__global__ __launch_bounds__(256, 2)
void gemmbf(const bf16* __restrict__ Ah, const bf16* __restrict__ Al, int lda,
            const bf16* __restrict__ Bh, const bf16* __restrict__ Bl, int ldb,
            float* __restrict__ C, int M, int N, int K,
            const float* __restrict__ bias)
{
    constexpr uint32_t OAL = 8192;
    constexpr uint32_t OBH = (TERMS == 3) ? 16384 : 8192;
    constexpr uint32_t OBL = 24576;
    constexpr uint32_t STG = (TERMS == 3) ? 32768 : 16384;

    extern __shared__ char smem[];
    const uint32_t sb = smem_u32(smem);
    const int tid = threadIdx.x, wid = tid >> 5, lane = tid & 31;
    const int m0 = blockIdx.y * 128, n0 = blockIdx.x * 128;
    const long kbeg = (long)blockIdx.z * K;
    if (gridDim.z > 1) C += (size_t)blockIdx.z * M * N;

    const int wm = wid >> 2, wn = wid & 3;

    const int r = tid >> 1;
    const int he = (tid & 1) * 16;
    const size_t arow_g = (size_t)(m0 + r) * lda + kbeg + he;
    const size_t brow_g = (size_t)(n0 + r) * ldb + kbeg + he;
    const bool bok = (n0 + r) < N;
    const uint32_t rowoff = (uint32_t)(r * 64 + (tid & 1) * 32);
    const uint32_t d0 = SW64(rowoff), d1 = SW64(rowoff + 16);

    const int g = lane >> 3, r8 = lane & 7;
    const int arow = wm * 64 + (g & 1) * 8 + r8;
    const int brow = wn * 32 + (g & 1) * 8 + r8;
    const int khalf = (g >> 1) * 16;

    float acc[4][4][4];
#pragma unroll
    for (int i = 0; i < 4; i++)
#pragma unroll
        for (int j = 0; j < 4; j++)
#pragma unroll
            for (int q = 0; q < 4; q++) acc[i][j][q] = 0.f;

    const int S = K / 32;

#define LOAD_STAGE(s)  do {                                                   \
        uint32_t base = sb + ((s) & 1) * STG;                                 \
        size_t ka = arow_g + (size_t)(s) * 32;                                \
        size_t kb = brow_g + (size_t)(s) * 32;                                \
        const bf16* pbh = bok ? (Bh + kb) : Bh;                               \
        int bs = bok ? 16 : 0;                                                \
        cp16(base + d0,        Ah + ka,     16);                              \
        cp16(base + d1,        Ah + ka + 8, 16);                              \
        cp16(base + OBH + d0,  pbh,         bs);                              \
        cp16(base + OBH + d1,  pbh + 8,     bs);                              \
        if (TERMS == 3) {                                                     \
            const bf16* pbl = bok ? (Bl + kb) : Bl;                           \
            cp16(base + OAL + d0,  Al + ka,     16);                          \
            cp16(base + OAL + d1,  Al + ka + 8, 16);                          \
            cp16(base + OBL + d0,  pbl,         bs);                          \
            cp16(base + OBL + d1,  pbl + 8,     bs);                          \
        }                                                                     \
        CP_COMMIT();                                                          \
    } while (0)

    LOAD_STAGE(0);

    for (int s = 0; s < S; s++) {
        if (s + 1 < S) { LOAD_STAGE(s + 1); CP_WAIT(1); }
        else           { CP_WAIT(0); }
        __syncthreads();

        const uint32_t pb = sb + (s & 1) * STG;
#pragma unroll
        for (int kc = 0; kc < 2; kc++) {
            uint32_t ah[4][4], al[4][4];
#pragma unroll
            for (int mt = 0; mt < 4; mt++) {
                uint32_t off = SW64((uint32_t)((arow + mt * 16) * 64 + kc * 32 + khalf));
                ldsm4(ah[mt], pb + off);
                if (TERMS == 3) ldsm4(al[mt], pb + OAL + off);
            }
#pragma unroll
            for (int np = 0; np < 2; np++) {
                uint32_t boffs = SW64((uint32_t)((brow + np * 16) * 64 + kc * 32 + khalf));
                uint32_t bh4[4], bl4[4];
                ldsm4(bh4, pb + OBH + boffs);
                if (TERMS == 3) ldsm4(bl4, pb + OBL + boffs);
#pragma unroll
                for (int mt = 0; mt < 4; mt++) {
                    mma16816(acc[mt][np * 2],     ah[mt], bh4[0], bh4[2]);
                    mma16816(acc[mt][np * 2 + 1], ah[mt], bh4[1], bh4[3]);
                    if (TERMS == 3) {
                        mma16816(acc[mt][np * 2],     ah[mt], bl4[0], bl4[2]);
                        mma16816(acc[mt][np * 2],     al[mt], bh4[0], bh4[2]);
                        mma16816(acc[mt][np * 2 + 1], ah[mt], bl4[1], bl4[3]);
                        mma16816(acc[mt][np * 2 + 1], al[mt], bh4[1], bh4[3]);
                    }
                }
            }
        }
        __syncthreads();
    }

    // epilogue
    const int gid = lane >> 2, tg = lane & 3;
#pragma unroll
    for (int mt = 0; mt < 4; mt++) {
#pragma unroll
        for (int nt = 0; nt < 4; nt++) {
            int gn = n0 + wn * 32 + nt * 8 + tg * 2;
            if (gn < N) {
                int gm = m0 + wm * 64 + mt * 16 + gid;
                float* cp0 = C + (size_t)gm * N + gn;
                float* cp1 = C + (size_t)(gm + 8) * N + gn;
                float2 v0 = make_float2(acc[mt][nt][0], acc[mt][nt][1]);
                float2 v1 = make_float2(acc[mt][nt][2], acc[mt][nt][3]);
                if (EPI == 1) {
                    float2 o0 = *(const float2*)cp0, o1 = *(const float2*)cp1;
                    v0.x += o0.x; v0.y += o0.y; v1.x += o1.x; v1.y += o1.y;
                } else if (EPI == 2) {
                    float b0 = bias[gn], b1 = bias[gn + 1];
                    v0.x = softplusf(v0.x + b0); v0.y = softplusf(v0.y + b1);
                    v1.x = softplusf(v1.x + b0); v1.y = softplusf(v1.y + b1);
                }
                *(float2*)cp0 = v0;
                *(float2*)cp1 = v1;
            }
        }
    }
#undef LOAD_STAGE
}

// ---------------- selective scan (writes bf16 hi of y) --------------------
__global__ __launch_bounds__(256)
void scan_kernel(const float* __restrict__ dt, const float* __restrict__ xm,
                 const float* __restrict__ xz, const float* __restrict__ dbc,
                 const float* __restrict__ A_log, const float* __restrict__ Dsk,
                 bf16* __restrict__ yh)
{
    int t = threadIdx.x;
    int s = t & 15;
    int d = blockIdx.x * 16 + (t >> 4);
    int b = blockIdx.y;
    float A  = -__expf(A_log[d * NS + s]);
    float Dv = Dsk[d];
    float h  = 0.f;
    for (int l = 0; l < SEQ; l++) {
        int m = b * SEQ + l;
        float dtv = dt[(size_t)m * DI + d];
        float xv  = xm[(size_t)m * DI + d];
        float Bv  = dbc[m * 96 + DTR + s];
        float Cv  = dbc[m * 96 + DTR + NS + s];
        float dA  = __expf(dtv * A);
        h = fmaf(dA, h, dtv * xv * Bv);
        float p = h * Cv;
        p += __shfl_xor_sync(0xffffffffu, p, 1);
        p += __shfl_xor_sync(0xffffffffu, p, 2);
        p += __shfl_xor_sync(0xffffffffu, p, 4);
        p += __shfl_xor_sync(0xffffffffu, p, 8);
        if (s == 0) {
            float zv = xz[(size_t)m * (2 * DI) + DI + d];
            float yv = p + xv * Dv;
            yv *= zv / (1.f + __expf(-zv));
            yh[(size_t)m * DI + d] = __float2bfloat16(yv);
        }
    }
}

// ---------------- driver ---------------------------------------------------
#define SMEM1 32768
#define SMEM3 65536
extern "C" void kernel_launch(void* const* d_in, const int* in_sizes, int n_in,
                              void* d_out, int out_size)
{
    const float* x_in   = (const float*)d_in[0];
    const float* in_w   = (const float*)d_in[1];
    const float* conv_w = (const float*)d_in[2];
    const float* conv_b = (const float*)d_in[3];
    const float* xp_w   = (const float*)d_in[4];
    const float* dt_w   = (const float*)d_in[5];
    const float* dt_b   = (const float*)d_in[6];
    const float* A_log  = (const float*)d_in[7];
    const float* D_sk   = (const float*)d_in[8];
    const float* out_w  = (const float*)d_in[9];
    const float* ln_g   = (const float*)d_in[10];
    const float* ln_b   = (const float*)d_in[11];
    float* out = (float*)d_out;

    float *px, *pxz, *pxm, *pdbcp, *pdbc, *pdt;
    bf16 *plnh, *pxmh, *pxml, *pdbch, *pdbcl, *pyh;
    bf16 *pwinh, *pwxph, *pwxpl, *pwdth, *pwdtl, *pwoh;
    cudaGetSymbolAddress((void**)&px,    g_x);
    cudaGetSymbolAddress((void**)&pxz,   g_xz);
    cudaGetSymbolAddress((void**)&pxm,   g_xm);
    cudaGetSymbolAddress((void**)&pdbcp, g_dbcp);
    cudaGetSymbolAddress((void**)&pdbc,  g_dbc);
    cudaGetSymbolAddress((void**)&pdt,   g_dt);
    cudaGetSymbolAddress((void**)&plnh,  g_lnh);
    cudaGetSymbolAddress((void**)&pxmh,  g_xmh);
    cudaGetSymbolAddress((void**)&pxml,  g_xml);
    cudaGetSymbolAddress((void**)&pdbch, g_dbch);
    cudaGetSymbolAddress((void**)&pdbcl, g_dbcl);
    cudaGetSymbolAddress((void**)&pyh,   g_yh);
    cudaGetSymbolAddress((void**)&pwinh, w_inh);
    cudaGetSymbolAddress((void**)&pwxph, w_xph);
    cudaGetSymbolAddress((void**)&pwxpl, w_xpl);
    cudaGetSymbolAddress((void**)&pwdth, w_dth);
    cudaGetSymbolAddress((void**)&pwdtl, w_dtl);
    cudaGetSymbolAddress((void**)&pwoh,  w_outh);

    cudaFuncSetAttribute(gemmbf<0,1>, cudaFuncAttributeMaxDynamicSharedMemorySize, SMEM1);
    cudaFuncSetAttribute(gemmbf<1,1>, cudaFuncAttributeMaxDynamicSharedMemorySize, SMEM1);
    cudaFuncSetAttribute(gemmbf<0,3>, cudaFuncAttributeMaxDynamicSharedMemorySize, SMEM3);
    cudaFuncSetAttribute(gemmbf<2,3>, cudaFuncAttributeMaxDynamicSharedMemorySize, SMEM3);

    // launch 1: residual init; launch 2: in_w convert; launch 3: ln(layer0);
    // launch 4: in_proj GEMM (ncu capture slot)
    copy_kernel<<<(MTOT * DM) / 256, 256>>>(x_in, px, MTOT * DM);
    cvt_hi<<<(NL * 2 * DI * DM / 8 + 255) / 256, 256>>>(in_w, pwinh, NL * 2 * DI * DM / 8);
    ln_kernel<1><<<MTOT, 256>>>(px, nullptr, plnh, ln_g, ln_b);
    gemmbf<0,1><<<dim3(32, 16, 1), 256, SMEM1>>>(
        plnh, plnh, DM, pwinh, pwinh, DM, pxz, MTOT, 2 * DI, DM, nullptr);

    // remaining weight conversions
    cvt_hi<<<(NL * DM * DI / 8 + 255) / 256, 256>>>(out_w, pwoh, NL * DM * DI / 8);
    cvt_split<<<(NL * 96 * DI / 8 + 255) / 256, 256>>>(xp_w, pwxph, pwxpl, NL * 96 * DI / 8);
    cvt_split<<<(NL * DI * DTR / 8 + 255) / 256, 256>>>(dt_w, pwdth, pwdtl, NL * DI * DTR / 8);

    for (int i = 0; i < NL; i++) {
        if (i > 0) {
            ln_kernel<1><<<MTOT, 256>>>(px, nullptr, plnh, ln_g, ln_b);
            gemmbf<0,1><<<dim3(32, 16, 1), 256, SMEM1>>>(
                plnh, plnh, DM, pwinh + (size_t)i * 2 * DI * DM,
                pwinh + (size_t)i * 2 * DI * DM, DM, pxz, MTOT, 2 * DI, DM, nullptr);
        }
        // depthwise conv + silu -> xm fp32 + hi/lo
        conv_silu<<<dim3(DI / 256, SEQ, BATCH), 256>>>(
            pxz, conv_w + (size_t)i * DI * DC, conv_b + (size_t)i * DI,
            pxm, pxmh, pxml);
        // x_proj (N=96, 3-term): split-K over 8 z-slices of K=256, then reduce
        gemmbf<0,3><<<dim3(1, 16, KSPLIT), 256, SMEM3>>>(
            pxmh, pxml, DI,
            pwxph + (size_t)i * 96 * DI, pwxpl + (size_t)i * 96 * DI, DI,
            pdbcp, MTOT, 96, DI / KSPLIT, nullptr);
        reduce8<<<(MTOT * 96) / 256, 256>>>(pdbcp, pdbc, pdbch, pdbcl);
        // dt_proj + bias + softplus (K=64, 3-term)
        gemmbf<2,3><<<dim3(16, 16, 1), 256, SMEM3>>>(
            pdbch, pdbcl, 96,
            pwdth + (size_t)i * DI * DTR, pwdtl + (size_t)i * DI * DTR, DTR,
            pdt, MTOT, DI, DTR, dt_b + (size_t)i * DI);
        // selective scan -> y hi
        scan_kernel<<<dim3(DI / 16, BATCH), 256>>>(
            pdt, pxm, pxz, pdbc, A_log + (size_t)i * DI * NS,
            D_sk + (size_t)i * DI, pyh);
        // out_proj accumulated into residual (K=2048, 1-term)
        gemmbf<1,1><<<dim3(8, 16, 1), 256, SMEM1>>>(
            pyh, pyh, DI,
            pwoh + (size_t)i * DM * DI, pwoh + (size_t)i * DM * DI, DI,
            px, MTOT, DM, DI, nullptr);
    }

    // final layernorm straight into d_out
    ln_kernel<0><<<MTOT, 256>>>(px, out, nullptr, ln_g, ln_b);
}

// round 10
// speedup vs baseline: 1.9046x; 1.9046x over previous
#include <cuda_runtime.h>
#include <cuda_bf16.h>
#include <cstdint>
#include <math.h>

#define NL    4
#define BATCH 2
#define SEQ   1024
#define DM    1024
#define DI    2048
#define DTR   64
#define NS    16
#define DC    4
#define MTOT  (BATCH*SEQ)   // 2048
#define KSPLIT 8

typedef __nv_bfloat16 bf16;

// ---------------- scratch (device globals; no allocation allowed) ----------
__device__ float g_x   [MTOT*DM];
__device__ float g_xzT [2*DI*MTOT];     // channel-major [feature, token] 32MB
__device__ float g_xmT [DI*MTOT];       // channel-major 16MB
__device__ float g_dtT [DI*MTOT];       // channel-major 16MB
__device__ float g_dbcp[KSPLIT*MTOT*96];
__device__ float g_dbc [MTOT*96];

__device__ __align__(128) bf16 g_lnh[MTOT*DM];
__device__ __align__(128) bf16 g_xmh[MTOT*DI];   // token-major (x_proj A)
__device__ __align__(128) bf16 g_xml[MTOT*DI];
__device__ __align__(128) bf16 g_dbch[MTOT*96];
__device__ __align__(128) bf16 g_dbcl[MTOT*96];
__device__ __align__(128) bf16 g_yh [MTOT*DI];   // token-major (out_proj A)
__device__ __align__(128) bf16 w_inh [NL*2*DI*DM];
__device__ __align__(128) bf16 w_xph [NL*96*DI];
__device__ __align__(128) bf16 w_xpl [NL*96*DI];
__device__ __align__(128) bf16 w_dth [NL*DI*DTR];
__device__ __align__(128) bf16 w_dtl [NL*DI*DTR];
__device__ __align__(128) bf16 w_outh[NL*DM*DI];

// ---------------- helpers --------------------------------------------------
__device__ __forceinline__ uint32_t smem_u32(const void* p) {
    uint32_t a;
    asm("{ .reg .u64 t; cvta.to.shared.u64 t, %1; cvt.u32.u64 %0, t; }"
        : "=r"(a) : "l"(p));
    return a;
}
__device__ __forceinline__ uint32_t swz128(uint32_t x) { return x ^ ((x >> 3) & 0x70u); }
__device__ __forceinline__ uint32_t swz64 (uint32_t x) { return x ^ ((x >> 3) & 0x30u); }

__device__ __forceinline__ void cp16(uint32_t dst, const void* src, int sz) {
    asm volatile("cp.async.cg.shared.global [%0], [%1], 16, %2;"
                 :: "r"(dst), "l"(src), "r"(sz) : "memory");
}
#define CP_COMMIT() asm volatile("cp.async.commit_group;" ::: "memory")
#define CP_WAIT(n)  asm volatile("cp.async.wait_group %0;" :: "n"(n) : "memory")

__device__ __forceinline__ void ldsm4(uint32_t* d, uint32_t addr) {
    asm volatile("ldmatrix.sync.aligned.m8n8.x4.shared.b16 {%0,%1,%2,%3}, [%4];"
        : "=r"(d[0]), "=r"(d[1]), "=r"(d[2]), "=r"(d[3]) : "r"(addr));
}
__device__ __forceinline__ void mma16816(float* c, const uint32_t* a,
                                         uint32_t b0, uint32_t b1) {
    asm volatile(
        "mma.sync.aligned.m16n8k16.row.col.f32.bf16.bf16.f32 "
        "{%0,%1,%2,%3}, {%4,%5,%6,%7}, {%8,%9}, {%0,%1,%2,%3};"
        : "+f"(c[0]), "+f"(c[1]), "+f"(c[2]), "+f"(c[3])
        : "r"(a[0]), "r"(a[1]), "r"(a[2]), "r"(a[3]), "r"(b0), "r"(b1));
}

__device__ __forceinline__ float softplusf(float v) {
    return (v > 20.f) ? v : log1pf(__expf(v));
}
__device__ __forceinline__ void split_bf16(float v, bf16* hp, bf16* lp) {
    bf16 h = __float2bfloat16(v);
    *hp = h;
    *lp = __float2bfloat16(v - __bfloat162float(h));
}

// ---------------- misc kernels --------------------------------------------
__global__ void copy_kernel(const float* __restrict__ a, float* __restrict__ o, int n) {
    int i = blockIdx.x * 256 + threadIdx.x;
    if (i < n) o[i] = a[i];
}
__global__ void cvt_hi(const float* __restrict__ src, bf16* __restrict__ hi, int n8) {
    int i = blockIdx.x * 256 + threadIdx.x;
    if (i >= n8) return;
    const float4* s = (const float4*)(src + (size_t)i * 8);
    float4 a = s[0], b = s[1];
    bf16 t[8];
    t[0]=__float2bfloat16(a.x); t[1]=__float2bfloat16(a.y);
    t[2]=__float2bfloat16(a.z); t[3]=__float2bfloat16(a.w);
    t[4]=__float2bfloat16(b.x); t[5]=__float2bfloat16(b.y);
    t[6]=__float2bfloat16(b.z); t[7]=__float2bfloat16(b.w);
    *(uint4*)(hi + (size_t)i * 8) = *(uint4*)t;
}
__global__ void cvt_split(const float* __restrict__ src, bf16* __restrict__ hi,
                          bf16* __restrict__ lo, int n8) {
    int i = blockIdx.x * 256 + threadIdx.x;
    if (i >= n8) return;
    const float4* s = (const float4*)(src + (size_t)i * 8);
    float4 a = s[0], b = s[1];
    float v[8] = {a.x, a.y, a.z, a.w, b.x, b.y, b.z, b.w};
    bf16 th[8], tl[8];
#pragma unroll
    for (int j = 0; j < 8; j++) {
        bf16 h = __float2bfloat16(v[j]);
        th[j] = h;
        tl[j] = __float2bfloat16(v[j] - __bfloat162float(h));
    }
    *(uint4*)(hi + (size_t)i * 8) = *(uint4*)th;
    *(uint4*)(lo + (size_t)i * 8) = *(uint4*)tl;
}

// ---------------- layernorm -------------------------------------------------
template<int BF>
__global__ __launch_bounds__(256)
void ln_kernel(const float* __restrict__ in, float* __restrict__ outp,
               bf16* __restrict__ oh,
               const float* __restrict__ gw, const float* __restrict__ bw)
{
    int row = blockIdx.x;
    int t = threadIdx.x;
    float4 v = ((const float4*)(in + (size_t)row * DM))[t];
    float s  = v.x + v.y + v.z + v.w;
    float s2 = v.x*v.x + v.y*v.y + v.z*v.z + v.w*v.w;
#pragma unroll
    for (int o = 16; o > 0; o >>= 1) {
        s  += __shfl_xor_sync(0xffffffffu, s,  o);
        s2 += __shfl_xor_sync(0xffffffffu, s2, o);
    }
    __shared__ float sh[16];
    if ((t & 31) == 0) { sh[t >> 5] = s; sh[(t >> 5) + 8] = s2; }
    __syncthreads();
    float S = 0.f, S2 = 0.f;
#pragma unroll
    for (int i = 0; i < 8; i++) { S += sh[i]; S2 += sh[i + 8]; }
    float mu  = S * (1.f / DM);
    float var = S2 * (1.f / DM) - mu * mu;
    float r   = rsqrtf(var + 1e-5f);
    float4 g = ((const float4*)gw)[t];
    float4 b = ((const float4*)bw)[t];
    float4 o4;
    o4.x = (v.x - mu) * r * g.x + b.x;
    o4.y = (v.y - mu) * r * g.y + b.y;
    o4.z = (v.z - mu) * r * g.z + b.z;
    o4.w = (v.w - mu) * r * g.w + b.w;
    if (BF) {
        bf16 t4[4] = {__float2bfloat16(o4.x), __float2bfloat16(o4.y),
                      __float2bfloat16(o4.z), __float2bfloat16(o4.w)};
        *(uint2*)(oh + (size_t)row * DM + t * 4) = *(uint2*)t4;
    } else {
        ((float4*)(outp + (size_t)row * DM))[t] = o4;
    }
}

// ---------------- channel-major causal conv (k=4) + SiLU -------------------
// xzT row d = channel d of xm part. Writes xmT (channel-major) and token-major
// bf16 hi/lo for x_proj's A operand.
__global__ __launch_bounds__(128)
void conv_silu_T(const float* __restrict__ xzT, const float* __restrict__ cw,
                 const float* __restrict__ cb, float* __restrict__ xmT,
                 bf16* __restrict__ oh, bf16* __restrict__ ol)
{
    int m = blockIdx.x * 128 + threadIdx.x;
    int d = blockIdx.y;
    int l = m & (SEQ - 1);
    const float* row = xzT + (size_t)d * MTOT;
    float w0 = cw[d*DC+0], w1 = cw[d*DC+1], w2 = cw[d*DC+2], w3 = cw[d*DC+3];
    float acc = cb[d];
    if (l >= 3) acc = fmaf(w0, row[m-3], acc);
    if (l >= 2) acc = fmaf(w1, row[m-2], acc);
    if (l >= 1) acc = fmaf(w2, row[m-1], acc);
    acc = fmaf(w3, row[m], acc);
    float sv = acc / (1.f + __expf(-acc));
    xmT[(size_t)d * MTOT + m] = sv;
    split_bf16(sv, oh + (size_t)m * DI + d, ol + (size_t)m * DI + d);
}

// ---------------- reduce split-K partials + bf16 split --------------------
__global__ void reduce8(const float* __restrict__ part, float* __restrict__ outp,
                        bf16* __restrict__ oh, bf16* __restrict__ ol)
{
    int i = blockIdx.x * 256 + threadIdx.x;
    float s = 0.f;
#pragma unroll
    for (int k = 0; k < KSPLIT; k++) s += part[(size_t)k * (MTOT * 96) + i];
    outp[i] = s;
    split_bf16(s, oh + i, ol + i);
}

// ---------------- bf16 GEMM, cp.async double-buffered ----------------------
// TERMS=1 (BK=64): C = Ah*Bh^T.  TERMS=3 (BK=32): ah*bh + ah*bl + al*bh.
// Block 128x128, 8 warps (2m x 4n), warp tile 64x32, 2 smem stages.
// EPI: 0 store, 1 C+=acc, 2 softplus(acc+bias[col]), 3 softplus(acc+bias[row])
// gridDim.z > 1 => split-K: z handles K-chunk [z*K,(z+1)*K), writes C + z*M*N.
template<int EPI, int TERMS>
__global__ __launch_bounds__(256, 2)
void gemmbf(const bf16* __restrict__ Ah, const bf16* __restrict__ Al, int lda,
            const bf16* __restrict__ Bh, const bf16* __restrict__ Bl, int ldb,
            float* __restrict__ C, int M, int N, int K,
            const float* __restrict__ bias)
{
    constexpr int BK   = (TERMS == 1) ? 64 : 32;
    constexpr int ROWB = BK * 2;            // bytes per smem row
    constexpr int NC   = BK / 16;           // cp16 per array per thread
    constexpr uint32_t OAL = 8192;
    constexpr uint32_t OBH = 16384;
    constexpr uint32_t OBL = 24576;
    constexpr uint32_t STG = 32768;

    extern __shared__ char smem[];
    const uint32_t sb = smem_u32(smem);
    const int tid = threadIdx.x, wid = tid >> 5, lane = tid & 31;
    const int m0 = blockIdx.y * 128, n0 = blockIdx.x * 128;
    const long kbeg = (long)blockIdx.z * K;
    if (gridDim.z > 1) C += (size_t)blockIdx.z * M * N;

    const int wm = wid >> 2, wn = wid & 3;

    const int r = tid >> 1, hh = tid & 1;
    const int helems = hh * (BK / 2);
    const size_t arow_g = (size_t)(m0 + r) * lda + kbeg + helems;
    const size_t brow_g = (size_t)(n0 + r) * ldb + kbeg + helems;
    const bool bok = (n0 + r) < N;
    uint32_t dsw[NC];
#pragma unroll
    for (int j = 0; j < NC; j++) {
        uint32_t v = (uint32_t)(r * ROWB + hh * (ROWB / 2) + j * 16);
        dsw[j] = (ROWB == 128) ? swz128(v) : swz64(v);
    }

    const int g = lane >> 3, r8 = lane & 7;
    const int arow = wm * 64 + (g & 1) * 8 + r8;
    const int brow = wn * 32 + (g & 1) * 8 + r8;
    const int khalf = (g >> 1) * 16;

    float acc[4][4][4];
#pragma unroll
    for (int i = 0; i < 4; i++)
#pragma unroll
        for (int j = 0; j < 4; j++)
#pragma unroll
            for (int q = 0; q < 4; q++) acc[i][j][q] = 0.f;

    const int S = K / BK;

#define LOAD_STAGE(s)  do {                                                   \
        uint32_t base = sb + ((s) & 1) * STG;                                 \
        size_t ka = arow_g + (size_t)(s) * BK;                                \
        size_t kb = brow_g + (size_t)(s) * BK;                                \
        const bf16* pbh = bok ? (Bh + kb) : Bh;                               \
        int bs = bok ? 16 : 0;                                                \
        _Pragma("unroll")                                                     \
        for (int j = 0; j < NC; j++) cp16(base + dsw[j], Ah + ka + j * 8, 16);\
        _Pragma("unroll")                                                     \
        for (int j = 0; j < NC; j++) cp16(base + OBH + dsw[j], pbh + j * 8, bs);\
        if (TERMS == 3) {                                                     \
            const bf16* pbl = bok ? (Bl + kb) : Bl;                           \
            _Pragma("unroll")                                                 \
            for (int j = 0; j < NC; j++) cp16(base + OAL + dsw[j], Al + ka + j * 8, 16);\
            _Pragma("unroll")                                                 \
            for (int j = 0; j < NC; j++) cp16(base + OBL + dsw[j], pbl + j * 8, bs);\
        }                                                                     \
        CP_COMMIT();                                                          \
    } while (0)

    LOAD_STAGE(0);

    for (int s = 0; s < S; s++) {
        if (s + 1 < S) { LOAD_STAGE(s + 1); CP_WAIT(1); }
        else           { CP_WAIT(0); }
        __syncthreads();

        const uint32_t pb = sb + (s & 1) * STG;
#pragma unroll
        for (int kc = 0; kc < BK / 16; kc++) {
            uint32_t ah[4][4], al[4][4];
#pragma unroll
            for (int mt = 0; mt < 4; mt++) {
                uint32_t v = (uint32_t)((arow + mt * 16) * ROWB + kc * 32 + khalf);
                uint32_t off = (ROWB == 128) ? swz128(v) : swz64(v);
                ldsm4(ah[mt], pb + off);
                if (TERMS == 3) ldsm4(al[mt], pb + OAL + off);
            }
#pragma unroll
            for (int np = 0; np < 2; np++) {
                uint32_t v = (uint32_t)((brow + np * 16) * ROWB + kc * 32 + khalf);
                uint32_t boffs = (ROWB == 128) ? swz128(v) : swz64(v);
                uint32_t bh4[4], bl4[4];
                ldsm4(bh4, pb + OBH + boffs);
                if (TERMS == 3) ldsm4(bl4, pb + OBL + boffs);
#pragma unroll
                for (int mt = 0; mt < 4; mt++) {
                    mma16816(acc[mt][np * 2],     ah[mt], bh4[0], bh4[2]);
                    mma16816(acc[mt][np * 2 + 1], ah[mt], bh4[1], bh4[3]);
                    if (TERMS == 3) {
                        mma16816(acc[mt][np * 2],     ah[mt], bl4[0], bl4[2]);
                        mma16816(acc[mt][np * 2],     al[mt], bh4[0], bh4[2]);
                        mma16816(acc[mt][np * 2 + 1], ah[mt], bl4[1], bl4[3]);
                        mma16816(acc[mt][np * 2 + 1], al[mt], bh4[1], bh4[3]);
                    }
                }
            }
        }
        __syncthreads();
    }

    // epilogue
    const int gid = lane >> 2, tg = lane & 3;
#pragma unroll
    for (int mt = 0; mt < 4; mt++) {
#pragma unroll
        for (int nt = 0; nt < 4; nt++) {
            int gn = n0 + wn * 32 + nt * 8 + tg * 2;
            if (gn < N) {
                int gm = m0 + wm * 64 + mt * 16 + gid;
                float* cp0 = C + (size_t)gm * N + gn;
                float* cp1 = C + (size_t)(gm + 8) * N + gn;
                float2 v0 = make_float2(acc[mt][nt][0], acc[mt][nt][1]);
                float2 v1 = make_float2(acc[mt][nt][2], acc[mt][nt][3]);
                if (EPI == 1) {
                    float2 o0 = *(const float2*)cp0, o1 = *(const float2*)cp1;
                    v0.x += o0.x; v0.y += o0.y; v1.x += o1.x; v1.y += o1.y;
                } else if (EPI == 2) {
                    float b0 = bias[gn], b1 = bias[gn + 1];
                    v0.x = softplusf(v0.x + b0); v0.y = softplusf(v0.y + b1);
                    v1.x = softplusf(v1.x + b0); v1.y = softplusf(v1.y + b1);
                } else if (EPI == 3) {
                    float b0 = bias[gm], b1 = bias[gm + 8];
                    v0.x = softplusf(v0.x + b0); v0.y = softplusf(v0.y + b0);
                    v1.x = softplusf(v1.x + b1); v1.y = softplusf(v1.y + b1);
                }
                *(float2*)cp0 = v0;
                *(float2*)cp1 = v1;
            }
        }
    }
#undef LOAD_STAGE
}

// ---------------- selective scan, channel-major operands -------------------
__global__ __launch_bounds__(256)
void scan_T(const float* __restrict__ dtT, const float* __restrict__ xmT,
            const float* __restrict__ xzT, const float* __restrict__ dbc,
            const float* __restrict__ A_log, const float* __restrict__ Dsk,
            bf16* __restrict__ yh)
{
    int t = threadIdx.x;
    int s = t & 15;
    int d = blockIdx.x * 16 + (t >> 4);
    int b = blockIdx.y;
    float A  = -__expf(A_log[d * NS + s]);
    float Dv = Dsk[d];
    const float* dtp = dtT + (size_t)d * MTOT + b * SEQ;
    const float* xmp = xmT + (size_t)d * MTOT + b * SEQ;
    const float* zp  = xzT + (size_t)(DI + d) * MTOT + b * SEQ;
    const float* bc  = dbc + (size_t)b * SEQ * 96;
    bf16* yp = yh + (size_t)b * SEQ * DI + d;
    float h = 0.f;
    for (int l = 0; l < SEQ; l++) {
        float dtv = dtp[l];
        float xv  = xmp[l];
        float Bv  = bc[l * 96 + DTR + s];
        float Cv  = bc[l * 96 + DTR + NS + s];
        float dA  = __expf(dtv * A);
        h = fmaf(dA, h, dtv * xv * Bv);
        float p = h * Cv;
        p += __shfl_xor_sync(0xffffffffu, p, 1);
        p += __shfl_xor_sync(0xffffffffu, p, 2);
        p += __shfl_xor_sync(0xffffffffu, p, 4);
        p += __shfl_xor_sync(0xffffffffu, p, 8);
        if (s == 0) {
            float zv = zp[l];
            float yv = p + xv * Dv;
            yv *= zv / (1.f + __expf(-zv));
            yp[(size_t)l * DI] = __float2bfloat16(yv);
        }
    }
}

// ---------------- driver ---------------------------------------------------
#define SMEM_G 65536
extern "C" void kernel_launch(void* const* d_in, const int* in_sizes, int n_in,
                              void* d_out, int out_size)
{
    const float* x_in   = (const float*)d_in[0];
    const float* in_w   = (const float*)d_in[1];
    const float* conv_w = (const float*)d_in[2];
    const float* conv_b = (const float*)d_in[3];
    const float* xp_w   = (const float*)d_in[4];
    const float* dt_w   = (const float*)d_in[5];
    const float* dt_b   = (const float*)d_in[6];
    const float* A_log  = (const float*)d_in[7];
    const float* D_sk   = (const float*)d_in[8];
    const float* out_w  = (const float*)d_in[9];
    const float* ln_g   = (const float*)d_in[10];
    const float* ln_b   = (const float*)d_in[11];
    float* out = (float*)d_out;

    float *px, *pxzT, *pxmT, *pdtT, *pdbcp, *pdbc;
    bf16 *plnh, *pxmh, *pxml, *pdbch, *pdbcl, *pyh;
    bf16 *pwinh, *pwxph, *pwxpl, *pwdth, *pwdtl, *pwoh;
    cudaGetSymbolAddress((void**)&px,    g_x);
    cudaGetSymbolAddress((void**)&pxzT,  g_xzT);
    cudaGetSymbolAddress((void**)&pxmT,  g_xmT);
    cudaGetSymbolAddress((void**)&pdtT,  g_dtT);
    cudaGetSymbolAddress((void**)&pdbcp, g_dbcp);
    cudaGetSymbolAddress((void**)&pdbc,  g_dbc);
    cudaGetSymbolAddress((void**)&plnh,  g_lnh);
    cudaGetSymbolAddress((void**)&pxmh,  g_xmh);
    cudaGetSymbolAddress((void**)&pxml,  g_xml);
    cudaGetSymbolAddress((void**)&pdbch, g_dbch);
    cudaGetSymbolAddress((void**)&pdbcl, g_dbcl);
    cudaGetSymbolAddress((void**)&pyh,   g_yh);
    cudaGetSymbolAddress((void**)&pwinh, w_inh);
    cudaGetSymbolAddress((void**)&pwxph, w_xph);
    cudaGetSymbolAddress((void**)&pwxpl, w_xpl);
    cudaGetSymbolAddress((void**)&pwdth, w_dth);
    cudaGetSymbolAddress((void**)&pwdtl, w_dtl);
    cudaGetSymbolAddress((void**)&pwoh,  w_outh);

    cudaFuncSetAttribute(gemmbf<0,1>, cudaFuncAttributeMaxDynamicSharedMemorySize, SMEM_G);
    cudaFuncSetAttribute(gemmbf<1,1>, cudaFuncAttributeMaxDynamicSharedMemorySize, SMEM_G);
    cudaFuncSetAttribute(gemmbf<0,3>, cudaFuncAttributeMaxDynamicSharedMemorySize, SMEM_G);
    cudaFuncSetAttribute(gemmbf<3,3>, cudaFuncAttributeMaxDynamicSharedMemorySize, SMEM_G);

    // launches 1-3
    copy_kernel<<<(MTOT * DM) / 256, 256>>>(x_in, px, MTOT * DM);
    cvt_hi<<<(NL * 2 * DI * DM / 8 + 255) / 256, 256>>>(in_w, pwinh, NL * 2 * DI * DM / 8);
    ln_kernel<1><<<MTOT, 256>>>(px, nullptr, plnh, ln_g, ln_b);
    // launch 4: PROBE scan (ncu capture slot) — deterministic on steady-state
    // buffers (zeros on first run); output overwritten by the real layer-0 scan.
    scan_T<<<dim3(DI / 16, BATCH), 256>>>(pdtT, pxmT, pxzT, pdbc,
                                          A_log, D_sk, pyh);
    // layer 0 in_proj (transposed out): xzT[2DI, MTOT]
    gemmbf<0,1><<<dim3(MTOT / 128, (2 * DI) / 128, 1), 256, SMEM_G>>>(
        pwinh, pwinh, DM, plnh, plnh, DM, pxzT, 2 * DI, MTOT, DM, nullptr);
    // remaining weight conversions
    cvt_hi<<<(NL * DM * DI / 8 + 255) / 256, 256>>>(out_w, pwoh, NL * DM * DI / 8);
    cvt_split<<<(NL * 96 * DI / 8 + 255) / 256, 256>>>(xp_w, pwxph, pwxpl, NL * 96 * DI / 8);
    cvt_split<<<(NL * DI * DTR / 8 + 255) / 256, 256>>>(dt_w, pwdth, pwdtl, NL * DI * DTR / 8);

    for (int i = 0; i < NL; i++) {
        if (i > 0) {
            ln_kernel<1><<<MTOT, 256>>>(px, nullptr, plnh, ln_g, ln_b);
            gemmbf<0,1><<<dim3(MTOT / 128, (2 * DI) / 128, 1), 256, SMEM_G>>>(
                pwinh + (size_t)i * 2 * DI * DM, pwinh, DM,
                plnh, plnh, DM, pxzT, 2 * DI, MTOT, DM, nullptr);
        }
        // channel-major conv + silu
        conv_silu_T<<<dim3(MTOT / 128, DI), 128>>>(
            pxzT, conv_w + (size_t)i * DI * DC, conv_b + (size_t)i * DI,
            pxmT, pxmh, pxml);
        // x_proj (token-major out [MTOT,96], 3-term, split-K 8)
        gemmbf<0,3><<<dim3(1, MTOT / 128, KSPLIT), 256, SMEM_G>>>(
            pxmh, pxml, DI,
            pwxph + (size_t)i * 96 * DI, pwxpl + (size_t)i * 96 * DI, DI,
            pdbcp, MTOT, 96, DI / KSPLIT, nullptr);
        reduce8<<<(MTOT * 96) / 256, 256>>>(pdbcp, pdbc, pdbch, pdbcl);
        // dt_proj transposed (dtT[DI, MTOT]) + row bias + softplus
        gemmbf<3,3><<<dim3(MTOT / 128, DI / 128, 1), 256, SMEM_G>>>(
            pwdth + (size_t)i * DI * DTR, pwdtl + (size_t)i * DI * DTR, DTR,
            pdbch, pdbcl, 96,
            pdtT, DI, MTOT, DTR, dt_b + (size_t)i * DI);
        // selective scan (channel-major reads, token-major y write)
        scan_T<<<dim3(DI / 16, BATCH), 256>>>(
            pdtT, pxmT, pxzT, pdbc, A_log + (size_t)i * DI * NS,
            D_sk + (size_t)i * DI, pyh);
        // out_proj accumulated into residual
        gemmbf<1,1><<<dim3(DM / 128, MTOT / 128, 1), 256, SMEM_G>>>(
            pyh, pyh, DI,
            pwoh + (size_t)i * DM * DI, pwoh, DI,
            px, MTOT, DM, DI, nullptr);
    }

    ln_kernel<0><<<MTOT, 256>>>(px, out, nullptr, ln_g, ln_b);
}

// round 11
// speedup vs baseline: 2.8086x; 1.4746x over previous
#include <cuda_runtime.h>
#include <cuda_bf16.h>
#include <cstdint>
#include <math.h>

#define NL    4
#define BATCH 2
#define SEQ   1024
#define DM    1024
#define DI    2048
#define DTR   64
#define NS    16
#define DC    4
#define MTOT  (BATCH*SEQ)   // 2048
#define KSPLIT 8
#define CH    128           // scan chunk length
#define NCH   (SEQ/CH)      // 8 chunks

typedef __nv_bfloat16 bf16;

// ---------------- scratch (device globals; no allocation allowed) ----------
__device__ float g_x   [MTOT*DM];
__device__ float g_xzT [2*DI*MTOT];     // channel-major [feature, token]
__device__ float g_xmT [DI*MTOT];       // channel-major
__device__ float g_dtT [DI*MTOT];       // channel-major
__device__ float g_dbcp[KSPLIT*MTOT*96];
__device__ float g_dbc [MTOT*96];

__device__ __align__(128) bf16 g_lnh[MTOT*DM];
__device__ __align__(128) bf16 g_xmh[MTOT*DI];
__device__ __align__(128) bf16 g_xml[MTOT*DI];
__device__ __align__(128) bf16 g_dbch[MTOT*96];
__device__ __align__(128) bf16 g_dbcl[MTOT*96];
__device__ __align__(128) bf16 g_yh [MTOT*DI];
__device__ __align__(128) bf16 w_inh [NL*2*DI*DM];
__device__ __align__(128) bf16 w_xph [NL*96*DI];
__device__ __align__(128) bf16 w_xpl [NL*96*DI];
__device__ __align__(128) bf16 w_dth [NL*DI*DTR];
__device__ __align__(128) bf16 w_dtl [NL*DI*DTR];
__device__ __align__(128) bf16 w_outh[NL*DM*DI];

// ---------------- helpers --------------------------------------------------
__device__ __forceinline__ uint32_t smem_u32(const void* p) {
    uint32_t a;
    asm("{ .reg .u64 t; cvta.to.shared.u64 t, %1; cvt.u32.u64 %0, t; }"
        : "=r"(a) : "l"(p));
    return a;
}
__device__ __forceinline__ uint32_t swz128(uint32_t x) { return x ^ ((x >> 3) & 0x70u); }
__device__ __forceinline__ uint32_t swz64 (uint32_t x) { return x ^ ((x >> 3) & 0x30u); }

__device__ __forceinline__ void cp16(uint32_t dst, const void* src, int sz) {
    asm volatile("cp.async.cg.shared.global [%0], [%1], 16, %2;"
                 :: "r"(dst), "l"(src), "r"(sz) : "memory");
}
#define CP_COMMIT() asm volatile("cp.async.commit_group;" ::: "memory")
#define CP_WAIT(n)  asm volatile("cp.async.wait_group %0;" :: "n"(n) : "memory")

__device__ __forceinline__ void ldsm4(uint32_t* d, uint32_t addr) {
    asm volatile("ldmatrix.sync.aligned.m8n8.x4.shared.b16 {%0,%1,%2,%3}, [%4];"
        : "=r"(d[0]), "=r"(d[1]), "=r"(d[2]), "=r"(d[3]) : "r"(addr));
}
__device__ __forceinline__ void mma16816(float* c, const uint32_t* a,
                                         uint32_t b0, uint32_t b1) {
    asm volatile(
        "mma.sync.aligned.m16n8k16.row.col.f32.bf16.bf16.f32 "
        "{%0,%1,%2,%3}, {%4,%5,%6,%7}, {%8,%9}, {%0,%1,%2,%3};"
        : "+f"(c[0]), "+f"(c[1]), "+f"(c[2]), "+f"(c[3])
        : "r"(a[0]), "r"(a[1]), "r"(a[2]), "r"(a[3]), "r"(b0), "r"(b1));
}

__device__ __forceinline__ float softplusf(float v) {
    return (v > 20.f) ? v : log1pf(__expf(v));
}
__device__ __forceinline__ void split_bf16(float v, bf16* hp, bf16* lp) {
    bf16 h = __float2bfloat16(v);
    *hp = h;
    *lp = __float2bfloat16(v - __bfloat162float(h));
}

// ---------------- misc kernels --------------------------------------------
__global__ void copy_kernel(const float* __restrict__ a, float* __restrict__ o, int n) {
    int i = blockIdx.x * 256 + threadIdx.x;
    if (i < n) o[i] = a[i];
}
__global__ void cvt_hi(const float* __restrict__ src, bf16* __restrict__ hi, int n8) {
    int i = blockIdx.x * 256 + threadIdx.x;
    if (i >= n8) return;
    const float4* s = (const float4*)(src + (size_t)i * 8);
    float4 a = s[0], b = s[1];
    bf16 t[8];
    t[0]=__float2bfloat16(a.x); t[1]=__float2bfloat16(a.y);
    t[2]=__float2bfloat16(a.z); t[3]=__float2bfloat16(a.w);
    t[4]=__float2bfloat16(b.x); t[5]=__float2bfloat16(b.y);
    t[6]=__float2bfloat16(b.z); t[7]=__float2bfloat16(b.w);
    *(uint4*)(hi + (size_t)i * 8) = *(uint4*)t;
}
__global__ void cvt_split(const float* __restrict__ src, bf16* __restrict__ hi,
                          bf16* __restrict__ lo, int n8) {
    int i = blockIdx.x * 256 + threadIdx.x;
    if (i >= n8) return;
    const float4* s = (const float4*)(src + (size_t)i * 8);
    float4 a = s[0], b = s[1];
    float v[8] = {a.x, a.y, a.z, a.w, b.x, b.y, b.z, b.w};
    bf16 th[8], tl[8];
#pragma unroll
    for (int j = 0; j < 8; j++) {
        bf16 h = __float2bfloat16(v[j]);
        th[j] = h;
        tl[j] = __float2bfloat16(v[j] - __bfloat162float(h));
    }
    *(uint4*)(hi + (size_t)i * 8) = *(uint4*)th;
    *(uint4*)(lo + (size_t)i * 8) = *(uint4*)tl;
}

// ---------------- layernorm -------------------------------------------------
template<int BF>
__global__ __launch_bounds__(256)
void ln_kernel(const float* __restrict__ in, float* __restrict__ outp,
               bf16* __restrict__ oh,
               const float* __restrict__ gw, const float* __restrict__ bw)
{
    int row = blockIdx.x;
    int t = threadIdx.x;
    float4 v = ((const float4*)(in + (size_t)row * DM))[t];
    float s  = v.x + v.y + v.z + v.w;
    float s2 = v.x*v.x + v.y*v.y + v.z*v.z + v.w*v.w;
#pragma unroll
    for (int o = 16; o > 0; o >>= 1) {
        s  += __shfl_xor_sync(0xffffffffu, s,  o);
        s2 += __shfl_xor_sync(0xffffffffu, s2, o);
    }
    __shared__ float sh[16];
    if ((t & 31) == 0) { sh[t >> 5] = s; sh[(t >> 5) + 8] = s2; }
    __syncthreads();
    float S = 0.f, S2 = 0.f;
#pragma unroll
    for (int i = 0; i < 8; i++) { S += sh[i]; S2 += sh[i + 8]; }
    float mu  = S * (1.f / DM);
    float var = S2 * (1.f / DM) - mu * mu;
    float r   = rsqrtf(var + 1e-5f);
    float4 g = ((const float4*)gw)[t];
    float4 b = ((const float4*)bw)[t];
    float4 o4;
    o4.x = (v.x - mu) * r * g.x + b.x;
    o4.y = (v.y - mu) * r * g.y + b.y;
    o4.z = (v.z - mu) * r * g.z + b.z;
    o4.w = (v.w - mu) * r * g.w + b.w;
    if (BF) {
        bf16 t4[4] = {__float2bfloat16(o4.x), __float2bfloat16(o4.y),
                      __float2bfloat16(o4.z), __float2bfloat16(o4.w)};
        *(uint2*)(oh + (size_t)row * DM + t * 4) = *(uint2*)t4;
    } else {
        ((float4*)(outp + (size_t)row * DM))[t] = o4;
    }
}

// ---------------- channel-major causal conv (k=4) + SiLU -------------------
__global__ __launch_bounds__(128)
void conv_silu_T(const float* __restrict__ xzT, const float* __restrict__ cw,
                 const float* __restrict__ cb, float* __restrict__ xmT,
                 bf16* __restrict__ oh, bf16* __restrict__ ol)
{
    int m = blockIdx.x * 128 + threadIdx.x;
    int d = blockIdx.y;
    int l = m & (SEQ - 1);
    const float* row = xzT + (size_t)d * MTOT;
    float w0 = cw[d*DC+0], w1 = cw[d*DC+1], w2 = cw[d*DC+2], w3 = cw[d*DC+3];
    float acc = cb[d];
    if (l >= 3) acc = fmaf(w0, row[m-3], acc);
    if (l >= 2) acc = fmaf(w1, row[m-2], acc);
    if (l >= 1) acc = fmaf(w2, row[m-1], acc);
    acc = fmaf(w3, row[m], acc);
    float sv = acc / (1.f + __expf(-acc));
    xmT[(size_t)d * MTOT + m] = sv;
    split_bf16(sv, oh + (size_t)m * DI + d, ol + (size_t)m * DI + d);
}

// ---------------- reduce split-K partials + bf16 split --------------------
__global__ void reduce8(const float* __restrict__ part, float* __restrict__ outp,
                        bf16* __restrict__ oh, bf16* __restrict__ ol)
{
    int i = blockIdx.x * 256 + threadIdx.x;
    float s = 0.f;
#pragma unroll
    for (int k = 0; k < KSPLIT; k++) s += part[(size_t)k * (MTOT * 96) + i];
    outp[i] = s;
    split_bf16(s, oh + i, ol + i);
}

// ---------------- bf16 GEMM, cp.async double-buffered ----------------------
template<int EPI, int TERMS>
__global__ __launch_bounds__(256, 2)
void gemmbf(const bf16* __restrict__ Ah, const bf16* __restrict__ Al, int lda,
            const bf16* __restrict__ Bh, const bf16* __restrict__ Bl, int ldb,
            float* __restrict__ C, int M, int N, int K,
            const float* __restrict__ bias)
{
    constexpr int BK   = (TERMS == 1) ? 64 : 32;
    constexpr int ROWB = BK * 2;
    constexpr int NC   = BK / 16;
    constexpr uint32_t OAL = 8192;
    constexpr uint32_t OBH = 16384;
    constexpr uint32_t OBL = 24576;
    constexpr uint32_t STG = 32768;

    extern __shared__ char smem[];
    const uint32_t sb = smem_u32(smem);
    const int tid = threadIdx.x, wid = tid >> 5, lane = tid & 31;
    const int m0 = blockIdx.y * 128, n0 = blockIdx.x * 128;
    const long kbeg = (long)blockIdx.z * K;
    if (gridDim.z > 1) C += (size_t)blockIdx.z * M * N;

    const int wm = wid >> 2, wn = wid & 3;

    const int r = tid >> 1, hh = tid & 1;
    const int helems = hh * (BK / 2);
    const size_t arow_g = (size_t)(m0 + r) * lda + kbeg + helems;
    const size_t brow_g = (size_t)(n0 + r) * ldb + kbeg + helems;
    const bool bok = (n0 + r) < N;
    uint32_t dsw[NC];
#pragma unroll
    for (int j = 0; j < NC; j++) {
        uint32_t v = (uint32_t)(r * ROWB + hh * (ROWB / 2) + j * 16);
        dsw[j] = (ROWB == 128) ? swz128(v) : swz64(v);
    }

    const int g = lane >> 3, r8 = lane & 7;
    const int arow = wm * 64 + (g & 1) * 8 + r8;
    const int brow = wn * 32 + (g & 1) * 8 + r8;
    const int khalf = (g >> 1) * 16;

    float acc[4][4][4];
#pragma unroll
    for (int i = 0; i < 4; i++)
#pragma unroll
        for (int j = 0; j < 4; j++)
#pragma unroll
            for (int q = 0; q < 4; q++) acc[i][j][q] = 0.f;

    const int S = K / BK;

#define LOAD_STAGE(s)  do {                                                   \
        uint32_t base = sb + ((s) & 1) * STG;                                 \
        size_t ka = arow_g + (size_t)(s) * BK;                                \
        size_t kb = brow_g + (size_t)(s) * BK;                                \
        const bf16* pbh = bok ? (Bh + kb) : Bh;                               \
        int bs = bok ? 16 : 0;                                                \
        _Pragma("unroll")                                                     \
        for (int j = 0; j < NC; j++) cp16(base + dsw[j], Ah + ka + j * 8, 16);\
        _Pragma("unroll")                                                     \
        for (int j = 0; j < NC; j++) cp16(base + OBH + dsw[j], pbh + j * 8, bs);\
        if (TERMS == 3) {                                                     \
            const bf16* pbl = bok ? (Bl + kb) : Bl;                           \
            _Pragma("unroll")                                                 \
            for (int j = 0; j < NC; j++) cp16(base + OAL + dsw[j], Al + ka + j * 8, 16);\
            _Pragma("unroll")                                                 \
            for (int j = 0; j < NC; j++) cp16(base + OBL + dsw[j], pbl + j * 8, bs);\
        }                                                                     \
        CP_COMMIT();                                                          \
    } while (0)

    LOAD_STAGE(0);

    for (int s = 0; s < S; s++) {
        if (s + 1 < S) { LOAD_STAGE(s + 1); CP_WAIT(1); }
        else           { CP_WAIT(0); }
        __syncthreads();

        const uint32_t pb = sb + (s & 1) * STG;
#pragma unroll
        for (int kc = 0; kc < BK / 16; kc++) {
            uint32_t ah[4][4], al[4][4];
#pragma unroll
            for (int mt = 0; mt < 4; mt++) {
                uint32_t v = (uint32_t)((arow + mt * 16) * ROWB + kc * 32 + khalf);
                uint32_t off = (ROWB == 128) ? swz128(v) : swz64(v);
                ldsm4(ah[mt], pb + off);
                if (TERMS == 3) ldsm4(al[mt], pb + OAL + off);
            }
#pragma unroll
            for (int np = 0; np < 2; np++) {
                uint32_t v = (uint32_t)((brow + np * 16) * ROWB + kc * 32 + khalf);
                uint32_t boffs = (ROWB == 128) ? swz128(v) : swz64(v);
                uint32_t bh4[4], bl4[4];
                ldsm4(bh4, pb + OBH + boffs);
                if (TERMS == 3) ldsm4(bl4, pb + OBL + boffs);
#pragma unroll
                for (int mt = 0; mt < 4; mt++) {
                    mma16816(acc[mt][np * 2],     ah[mt], bh4[0], bh4[2]);
                    mma16816(acc[mt][np * 2 + 1], ah[mt], bh4[1], bh4[3]);
                    if (TERMS == 3) {
                        mma16816(acc[mt][np * 2],     ah[mt], bl4[0], bl4[2]);
                        mma16816(acc[mt][np * 2],     al[mt], bh4[0], bh4[2]);
                        mma16816(acc[mt][np * 2 + 1], ah[mt], bl4[1], bl4[3]);
                        mma16816(acc[mt][np * 2 + 1], al[mt], bh4[1], bh4[3]);
                    }
                }
            }
        }
        __syncthreads();
    }

    // epilogue
    const int gid = lane >> 2, tg = lane & 3;
#pragma unroll
    for (int mt = 0; mt < 4; mt++) {
#pragma unroll
        for (int nt = 0; nt < 4; nt++) {
            int gn = n0 + wn * 32 + nt * 8 + tg * 2;
            if (gn < N) {
                int gm = m0 + wm * 64 + mt * 16 + gid;
                float* cp0 = C + (size_t)gm * N + gn;
                float* cp1 = C + (size_t)(gm + 8) * N + gn;
                float2 v0 = make_float2(acc[mt][nt][0], acc[mt][nt][1]);
                float2 v1 = make_float2(acc[mt][nt][2], acc[mt][nt][3]);
                if (EPI == 1) {
                    float2 o0 = *(const float2*)cp0, o1 = *(const float2*)cp1;
                    v0.x += o0.x; v0.y += o0.y; v1.x += o1.x; v1.y += o1.y;
                } else if (EPI == 2) {
                    float b0 = bias[gn], b1 = bias[gn + 1];
                    v0.x = softplusf(v0.x + b0); v0.y = softplusf(v0.y + b1);
                    v1.x = softplusf(v1.x + b0); v1.y = softplusf(v1.y + b1);
                } else if (EPI == 3) {
                    float b0 = bias[gm], b1 = bias[gm + 8];
                    v0.x = softplusf(v0.x + b0); v0.y = softplusf(v0.y + b0);
                    v1.x = softplusf(v1.x + b1); v1.y = softplusf(v1.y + b1);
                }
                *(float2*)cp0 = v0;
                *(float2*)cp1 = v1;
            }
        }
    }
#undef LOAD_STAGE
}

// ---------------- chunked parallel selective scan ---------------------------
// Linear recurrence h_t = dA_t h_{t-1} + dBu_t split into NCH chunks of CH.
// Block: 256 thr = 2 d-channels x NCH chunks x 16 states.
// Phase A: chunk-local scan from 0, keep (prod dA, carry).
// Phase B: serial combine of NCH chunk summaries -> per-chunk h_init (smem).
// Phase C: re-scan chunk from h_init, emit y (16-lane shfl reduce over states).
__global__ __launch_bounds__(256)
void scan_chunked(const float* __restrict__ dtT, const float* __restrict__ xmT,
                  const float* __restrict__ xzT, const float* __restrict__ dbc,
                  const float* __restrict__ A_log, const float* __restrict__ Dsk,
                  bf16* __restrict__ yh)
{
    int t  = threadIdx.x;
    int s  = t & 15;
    int c  = (t >> 4) & (NCH - 1);
    int dl = t >> 7;                      // 0..1
    int d  = blockIdx.x * 2 + dl;
    int b  = blockIdx.y;

    float A = -__expf(A_log[d * NS + s]);
    const float* dtp = dtT + (size_t)d * MTOT + b * SEQ + c * CH;
    const float* xmp = xmT + (size_t)d * MTOT + b * SEQ + c * CH;
    const float* bc  = dbc + ((size_t)b * SEQ + c * CH) * 96;

    // Phase A: local scan from 0
    float aprod = 1.f, bcar = 0.f;
#pragma unroll 4
    for (int l = 0; l < CH; l++) {
        float dtv = dtp[l];
        float xv  = xmp[l];
        float Bv  = bc[l * 96 + DTR + s];
        float dA  = __expf(dtv * A);
        aprod *= dA;
        bcar = fmaf(dA, bcar, dtv * xv * Bv);
    }

    __shared__ float sA[2][NCH][16];
    __shared__ float sB[2][NCH][16];
    sA[dl][c][s] = aprod;
    sB[dl][c][s] = bcar;
    __syncthreads();

    // Phase B: serial combine (one thread per (dl,s))
    if (c == 0) {
        float h = 0.f;
#pragma unroll
        for (int cc = 0; cc < NCH; cc++) {
            float a  = sA[dl][cc][s];
            float bb = sB[dl][cc][s];
            sB[dl][cc][s] = h;            // h_init for chunk cc
            h = fmaf(a, h, bb);
        }
    }
    __syncthreads();

    // Phase C: replay with correct initial state, emit y
    float h  = sB[dl][c][s];
    float Dv = Dsk[d];
    const float* zp = xzT + (size_t)(DI + d) * MTOT + b * SEQ + c * CH;
    bf16* yp = yh + ((size_t)b * SEQ + c * CH) * DI + d;
#pragma unroll 4
    for (int l = 0; l < CH; l++) {
        float dtv = dtp[l];
        float xv  = xmp[l];
        float Bv  = bc[l * 96 + DTR + s];
        float Cv  = bc[l * 96 + DTR + NS + s];
        float dA  = __expf(dtv * A);
        h = fmaf(dA, h, dtv * xv * Bv);
        float p = h * Cv;
        p += __shfl_xor_sync(0xffffffffu, p, 1);
        p += __shfl_xor_sync(0xffffffffu, p, 2);
        p += __shfl_xor_sync(0xffffffffu, p, 4);
        p += __shfl_xor_sync(0xffffffffu, p, 8);
        if (s == 0) {
            float zv = zp[l];
            float yv = p + xv * Dv;
            yv *= zv / (1.f + __expf(-zv));
            yp[(size_t)l * DI] = __float2bfloat16(yv);
        }
    }
}

// ---------------- driver ---------------------------------------------------
#define SMEM_G 65536
extern "C" void kernel_launch(void* const* d_in, const int* in_sizes, int n_in,
                              void* d_out, int out_size)
{
    const float* x_in   = (const float*)d_in[0];
    const float* in_w   = (const float*)d_in[1];
    const float* conv_w = (const float*)d_in[2];
    const float* conv_b = (const float*)d_in[3];
    const float* xp_w   = (const float*)d_in[4];
    const float* dt_w   = (const float*)d_in[5];
    const float* dt_b   = (const float*)d_in[6];
    const float* A_log  = (const float*)d_in[7];
    const float* D_sk   = (const float*)d_in[8];
    const float* out_w  = (const float*)d_in[9];
    const float* ln_g   = (const float*)d_in[10];
    const float* ln_b   = (const float*)d_in[11];
    float* out = (float*)d_out;

    float *px, *pxzT, *pxmT, *pdtT, *pdbcp, *pdbc;
    bf16 *plnh, *pxmh, *pxml, *pdbch, *pdbcl, *pyh;
    bf16 *pwinh, *pwxph, *pwxpl, *pwdth, *pwdtl, *pwoh;
    cudaGetSymbolAddress((void**)&px,    g_x);
    cudaGetSymbolAddress((void**)&pxzT,  g_xzT);
    cudaGetSymbolAddress((void**)&pxmT,  g_xmT);
    cudaGetSymbolAddress((void**)&pdtT,  g_dtT);
    cudaGetSymbolAddress((void**)&pdbcp, g_dbcp);
    cudaGetSymbolAddress((void**)&pdbc,  g_dbc);
    cudaGetSymbolAddress((void**)&plnh,  g_lnh);
    cudaGetSymbolAddress((void**)&pxmh,  g_xmh);
    cudaGetSymbolAddress((void**)&pxml,  g_xml);
    cudaGetSymbolAddress((void**)&pdbch, g_dbch);
    cudaGetSymbolAddress((void**)&pdbcl, g_dbcl);
    cudaGetSymbolAddress((void**)&pyh,   g_yh);
    cudaGetSymbolAddress((void**)&pwinh, w_inh);
    cudaGetSymbolAddress((void**)&pwxph, w_xph);
    cudaGetSymbolAddress((void**)&pwxpl, w_xpl);
    cudaGetSymbolAddress((void**)&pwdth, w_dth);
    cudaGetSymbolAddress((void**)&pwdtl, w_dtl);
    cudaGetSymbolAddress((void**)&pwoh,  w_outh);

    cudaFuncSetAttribute(gemmbf<0,1>, cudaFuncAttributeMaxDynamicSharedMemorySize, SMEM_G);
    cudaFuncSetAttribute(gemmbf<1,1>, cudaFuncAttributeMaxDynamicSharedMemorySize, SMEM_G);
    cudaFuncSetAttribute(gemmbf<0,3>, cudaFuncAttributeMaxDynamicSharedMemorySize, SMEM_G);
    cudaFuncSetAttribute(gemmbf<3,3>, cudaFuncAttributeMaxDynamicSharedMemorySize, SMEM_G);

    // launches 1-3
    copy_kernel<<<(MTOT * DM) / 256, 256>>>(x_in, px, MTOT * DM);
    cvt_hi<<<(NL * 2 * DI * DM / 8 + 255) / 256, 256>>>(in_w, pwinh, NL * 2 * DI * DM / 8);
    ln_kernel<1><<<MTOT, 256>>>(px, nullptr, plnh, ln_g, ln_b);
    // launch 4: PROBE chunked scan (ncu capture slot); deterministic on
    // steady-state buffers, output overwritten by real layer-0 scan.
    scan_chunked<<<dim3(DI / 2, BATCH), 256>>>(pdtT, pxmT, pxzT, pdbc,
                                               A_log, D_sk, pyh);
    // layer 0 in_proj (transposed out): xzT[2DI, MTOT]
    gemmbf<0,1><<<dim3(MTOT / 128, (2 * DI) / 128, 1), 256, SMEM_G>>>(
        pwinh, pwinh, DM, plnh, plnh, DM, pxzT, 2 * DI, MTOT, DM, nullptr);
    // remaining weight conversions
    cvt_hi<<<(NL * DM * DI / 8 + 255) / 256, 256>>>(out_w, pwoh, NL * DM * DI / 8);
    cvt_split<<<(NL * 96 * DI / 8 + 255) / 256, 256>>>(xp_w, pwxph, pwxpl, NL * 96 * DI / 8);
    cvt_split<<<(NL * DI * DTR / 8 + 255) / 256, 256>>>(dt_w, pwdth, pwdtl, NL * DI * DTR / 8);

    for (int i = 0; i < NL; i++) {
        if (i > 0) {
            ln_kernel<1><<<MTOT, 256>>>(px, nullptr, plnh, ln_g, ln_b);
            gemmbf<0,1><<<dim3(MTOT / 128, (2 * DI) / 128, 1), 256, SMEM_G>>>(
                pwinh + (size_t)i * 2 * DI * DM, pwinh, DM,
                plnh, plnh, DM, pxzT, 2 * DI, MTOT, DM, nullptr);
        }
        // channel-major conv + silu
        conv_silu_T<<<dim3(MTOT / 128, DI), 128>>>(
            pxzT, conv_w + (size_t)i * DI * DC, conv_b + (size_t)i * DI,
            pxmT, pxmh, pxml);
        // x_proj (token-major out [MTOT,96], 3-term, split-K 8)
        gemmbf<0,3><<<dim3(1, MTOT / 128, KSPLIT), 256, SMEM_G>>>(
            pxmh, pxml, DI,
            pwxph + (size_t)i * 96 * DI, pwxpl + (size_t)i * 96 * DI, DI,
            pdbcp, MTOT, 96, DI / KSPLIT, nullptr);
        reduce8<<<(MTOT * 96) / 256, 256>>>(pdbcp, pdbc, pdbch, pdbcl);
        // dt_proj transposed (dtT[DI, MTOT]) + row bias + softplus
        gemmbf<3,3><<<dim3(MTOT / 128, DI / 128, 1), 256, SMEM_G>>>(
            pwdth + (size_t)i * DI * DTR, pwdtl + (size_t)i * DI * DTR, DTR,
            pdbch, pdbcl, 96,
            pdtT, DI, MTOT, DTR, dt_b + (size_t)i * DI);
        // chunked parallel scan
        scan_chunked<<<dim3(DI / 2, BATCH), 256>>>(
            pdtT, pxmT, pxzT, pdbc, A_log + (size_t)i * DI * NS,
            D_sk + (size_t)i * DI, pyh);
        // out_proj accumulated into residual
        gemmbf<1,1><<<dim3(DM / 128, MTOT / 128, 1), 256, SMEM_G>>>(
            pyh, pyh, DI,
            pwoh + (size_t)i * DM * DI, pwoh, DI,
            px, MTOT, DM, DI, nullptr);
    }

    ln_kernel<0><<<MTOT, 256>>>(px, out, nullptr, ln_g, ln_b);
}

// round 12
// speedup vs baseline: 4.6784x; 1.6658x over previous
#include <cuda_runtime.h>
#include <cuda_bf16.h>
#include <cstdint>
#include <math.h>

#define NL    4
#define BATCH 2
#define SEQ   1024
#define DM    1024
#define DI    2048
#define DTR   64
#define NS    16
#define DC    4
#define MTOT  (BATCH*SEQ)   // 2048
#define KSPLIT 8
#define NCH   32            // scan chunks
#define CH    32            // chunk length (NCH*CH = SEQ)

typedef __nv_bfloat16 bf16;

// ---------------- scratch (device globals; no allocation allowed) ----------
__device__ float g_x   [MTOT*DM];
__device__ float g_xz  [MTOT*2*DI];     // token-major
__device__ float g_xm  [MTOT*DI];       // token-major fp32
__device__ float g_dt  [MTOT*DI];       // token-major fp32
__device__ float g_dbcp[KSPLIT*MTOT*96];
__device__ float g_dbc [MTOT*96];
__device__ float g_sa  [BATCH*NCH*DI*NS];   // chunk prod(dA)
__device__ float g_sb  [BATCH*NCH*DI*NS];   // chunk carry
__device__ float g_hin [BATCH*NCH*DI*NS];   // per-chunk initial state

__device__ __align__(128) bf16 g_lnh[MTOT*DM];
__device__ __align__(128) bf16 g_xmh[MTOT*DI];
__device__ __align__(128) bf16 g_xml[MTOT*DI];
__device__ __align__(128) bf16 g_dbch[MTOT*96];
__device__ __align__(128) bf16 g_dbcl[MTOT*96];
__device__ __align__(128) bf16 g_yh [MTOT*DI];
__device__ __align__(128) bf16 w_inh [NL*2*DI*DM];
__device__ __align__(128) bf16 w_xph [NL*96*DI];
__device__ __align__(128) bf16 w_xpl [NL*96*DI];
__device__ __align__(128) bf16 w_dth [NL*DI*DTR];
__device__ __align__(128) bf16 w_dtl [NL*DI*DTR];
__device__ __align__(128) bf16 w_outh[NL*DM*DI];

// ---------------- helpers --------------------------------------------------
__device__ __forceinline__ uint32_t smem_u32(const void* p) {
    uint32_t a;
    asm("{ .reg .u64 t; cvta.to.shared.u64 t, %1; cvt.u32.u64 %0, t; }"
        : "=r"(a) : "l"(p));
    return a;
}
__device__ __forceinline__ uint32_t swz128(uint32_t x) { return x ^ ((x >> 3) & 0x70u); }
__device__ __forceinline__ uint32_t swz64 (uint32_t x) { return x ^ ((x >> 3) & 0x30u); }
__device__ __forceinline__ float ex2f(float x) {
    float r; asm("ex2.approx.ftz.f32 %0, %1;" : "=f"(r) : "f"(x)); return r;
}

__device__ __forceinline__ void cp16(uint32_t dst, const void* src, int sz) {
    asm volatile("cp.async.cg.shared.global [%0], [%1], 16, %2;"
                 :: "r"(dst), "l"(src), "r"(sz) : "memory");
}
#define CP_COMMIT() asm volatile("cp.async.commit_group;" ::: "memory")
#define CP_WAIT(n)  asm volatile("cp.async.wait_group %0;" :: "n"(n) : "memory")

__device__ __forceinline__ void ldsm4(uint32_t* d, uint32_t addr) {
    asm volatile("ldmatrix.sync.aligned.m8n8.x4.shared.b16 {%0,%1,%2,%3}, [%4];"
        : "=r"(d[0]), "=r"(d[1]), "=r"(d[2]), "=r"(d[3]) : "r"(addr));
}
__device__ __forceinline__ void mma16816(float* c, const uint32_t* a,
                                         uint32_t b0, uint32_t b1) {
    asm volatile(
        "mma.sync.aligned.m16n8k16.row.col.f32.bf16.bf16.f32 "
        "{%0,%1,%2,%3}, {%4,%5,%6,%7}, {%8,%9}, {%0,%1,%2,%3};"
        : "+f"(c[0]), "+f"(c[1]), "+f"(c[2]), "+f"(c[3])
        : "r"(a[0]), "r"(a[1]), "r"(a[2]), "r"(a[3]), "r"(b0), "r"(b1));
}

__device__ __forceinline__ float softplusf(float v) {
    return (v > 20.f) ? v : log1pf(__expf(v));
}
__device__ __forceinline__ void split_bf16(float v, bf16* hp, bf16* lp) {
    bf16 h = __float2bfloat16(v);
    *hp = h;
    *lp = __float2bfloat16(v - __bfloat162float(h));
}

// ---------------- misc kernels --------------------------------------------
__global__ void copy_kernel(const float* __restrict__ a, float* __restrict__ o, int n) {
    int i = blockIdx.x * 256 + threadIdx.x;
    if (i < n) o[i] = a[i];
}
__global__ void cvt_hi(const float* __restrict__ src, bf16* __restrict__ hi, int n8) {
    int i = blockIdx.x * 256 + threadIdx.x;
    if (i >= n8) return;
    const float4* s = (const float4*)(src + (size_t)i * 8);
    float4 a = s[0], b = s[1];
    bf16 t[8];
    t[0]=__float2bfloat16(a.x); t[1]=__float2bfloat16(a.y);
    t[2]=__float2bfloat16(a.z); t[3]=__float2bfloat16(a.w);
    t[4]=__float2bfloat16(b.x); t[5]=__float2bfloat16(b.y);
    t[6]=__float2bfloat16(b.z); t[7]=__float2bfloat16(b.w);
    *(uint4*)(hi + (size_t)i * 8) = *(uint4*)t;
}
__global__ void cvt_split(const float* __restrict__ src, bf16* __restrict__ hi,
                          bf16* __restrict__ lo, int n8) {
    int i = blockIdx.x * 256 + threadIdx.x;
    if (i >= n8) return;
    const float4* s = (const float4*)(src + (size_t)i * 8);
    float4 a = s[0], b = s[1];
    float v[8] = {a.x, a.y, a.z, a.w, b.x, b.y, b.z, b.w};
    bf16 th[8], tl[8];
#pragma unroll
    for (int j = 0; j < 8; j++) {
        bf16 h = __float2bfloat16(v[j]);
        th[j] = h;
        tl[j] = __float2bfloat16(v[j] - __bfloat162float(h));
    }
    *(uint4*)(hi + (size_t)i * 8) = *(uint4*)th;
    *(uint4*)(lo + (size_t)i * 8) = *(uint4*)tl;
}

// ---------------- layernorm -------------------------------------------------
template<int BF>
__global__ __launch_bounds__(256)
void ln_kernel(const float* __restrict__ in, float* __restrict__ outp,
               bf16* __restrict__ oh,
               const float* __restrict__ gw, const float* __restrict__ bw)
{
    int row = blockIdx.x;
    int t = threadIdx.x;
    float4 v = ((const float4*)(in + (size_t)row * DM))[t];
    float s  = v.x + v.y + v.z + v.w;
    float s2 = v.x*v.x + v.y*v.y + v.z*v.z + v.w*v.w;
#pragma unroll
    for (int o = 16; o > 0; o >>= 1) {
        s  += __shfl_xor_sync(0xffffffffu, s,  o);
        s2 += __shfl_xor_sync(0xffffffffu, s2, o);
    }
    __shared__ float sh[16];
    if ((t & 31) == 0) { sh[t >> 5] = s; sh[(t >> 5) + 8] = s2; }
    __syncthreads();
    float S = 0.f, S2 = 0.f;
#pragma unroll
    for (int i = 0; i < 8; i++) { S += sh[i]; S2 += sh[i + 8]; }
    float mu  = S * (1.f / DM);
    float var = S2 * (1.f / DM) - mu * mu;
    float r   = rsqrtf(var + 1e-5f);
    float4 g = ((const float4*)gw)[t];
    float4 b = ((const float4*)bw)[t];
    float4 o4;
    o4.x = (v.x - mu) * r * g.x + b.x;
    o4.y = (v.y - mu) * r * g.y + b.y;
    o4.z = (v.z - mu) * r * g.z + b.z;
    o4.w = (v.w - mu) * r * g.w + b.w;
    if (BF) {
        bf16 t4[4] = {__float2bfloat16(o4.x), __float2bfloat16(o4.y),
                      __float2bfloat16(o4.z), __float2bfloat16(o4.w)};
        *(uint2*)(oh + (size_t)row * DM + t * 4) = *(uint2*)t4;
    } else {
        ((float4*)(outp + (size_t)row * DM))[t] = o4;
    }
}

// ---------------- token-major causal conv (k=4) + SiLU + bf16 split --------
__global__ __launch_bounds__(256)
void conv_silu(const float* __restrict__ xz, const float* __restrict__ cw,
               const float* __restrict__ cb, float* __restrict__ xmout,
               bf16* __restrict__ oh, bf16* __restrict__ ol)
{
    int d = blockIdx.x * 256 + threadIdx.x;
    int l = blockIdx.y;
    int b = blockIdx.z;
    float acc = cb[d];
#pragma unroll
    for (int j = 0; j < DC; j++) {
        int lj = l - (DC - 1) + j;
        if (lj >= 0)
            acc = fmaf(cw[d * DC + j], xz[(size_t)(b * SEQ + lj) * (2 * DI) + d], acc);
    }
    float sv = acc / (1.f + __expf(-acc));
    size_t o = (size_t)(b * SEQ + l) * DI + d;
    xmout[o] = sv;
    split_bf16(sv, oh + o, ol + o);
}

// ---------------- reduce split-K partials + bf16 split --------------------
__global__ void reduce8(const float* __restrict__ part, float* __restrict__ outp,
                        bf16* __restrict__ oh, bf16* __restrict__ ol)
{
    int i = blockIdx.x * 256 + threadIdx.x;
    float s = 0.f;
#pragma unroll
    for (int k = 0; k < KSPLIT; k++) s += part[(size_t)k * (MTOT * 96) + i];
    outp[i] = s;
    split_bf16(s, oh + i, ol + i);
}

// ---------------- bf16 GEMM, cp.async double-buffered ----------------------
// TERMS=1 (BK=64): C = Ah*Bh^T.  TERMS=3 (BK=32): ah*bh + ah*bl + al*bh.
// EPI: 0 store, 1 C+=acc, 2 softplus(acc+bias[col])
template<int EPI, int TERMS>
__global__ __launch_bounds__(256, 2)
void gemmbf(const bf16* __restrict__ Ah, const bf16* __restrict__ Al, int lda,
            const bf16* __restrict__ Bh, const bf16* __restrict__ Bl, int ldb,
            float* __restrict__ C, int M, int N, int K,
            const float* __restrict__ bias)
{
    constexpr int BK   = (TERMS == 1) ? 64 : 32;
    constexpr int ROWB = BK * 2;
    constexpr int NC   = BK / 16;
    constexpr uint32_t OAL = 8192;
    constexpr uint32_t OBH = 16384;
    constexpr uint32_t OBL = 24576;
    constexpr uint32_t STG = 32768;

    extern __shared__ char smem[];
    const uint32_t sb = smem_u32(smem);
    const int tid = threadIdx.x, wid = tid >> 5, lane = tid & 31;
    const int m0 = blockIdx.y * 128, n0 = blockIdx.x * 128;
    const long kbeg = (long)blockIdx.z * K;
    if (gridDim.z > 1) C += (size_t)blockIdx.z * M * N;

    const int wm = wid >> 2, wn = wid & 3;

    const int r = tid >> 1, hh = tid & 1;
    const int helems = hh * (BK / 2);
    const size_t arow_g = (size_t)(m0 + r) * lda + kbeg + helems;
    const size_t brow_g = (size_t)(n0 + r) * ldb + kbeg + helems;
    const bool bok = (n0 + r) < N;
    uint32_t dsw[NC];
#pragma unroll
    for (int j = 0; j < NC; j++) {
        uint32_t v = (uint32_t)(r * ROWB + hh * (ROWB / 2) + j * 16);
        dsw[j] = (ROWB == 128) ? swz128(v) : swz64(v);
    }

    const int g = lane >> 3, r8 = lane & 7;
    const int arow = wm * 64 + (g & 1) * 8 + r8;
    const int brow = wn * 32 + (g & 1) * 8 + r8;
    const int khalf = (g >> 1) * 16;

    float acc[4][4][4];
#pragma unroll
    for (int i = 0; i < 4; i++)
#pragma unroll
        for (int j = 0; j < 4; j++)
#pragma unroll
            for (int q = 0; q < 4; q++) acc[i][j][q] = 0.f;

    const int S = K / BK;

#define LOAD_STAGE(s)  do {                                                   \
        uint32_t base = sb + ((s) & 1) * STG;                                 \
        size_t ka = arow_g + (size_t)(s) * BK;                                \
        size_t kb = brow_g + (size_t)(s) * BK;                                \
        const bf16* pbh = bok ? (Bh + kb) : Bh;                               \
        int bs = bok ? 16 : 0;                                                \
        _Pragma("unroll")                                                     \
        for (int j = 0; j < NC; j++) cp16(base + dsw[j], Ah + ka + j * 8, 16);\
        _Pragma("unroll")                                                     \
        for (int j = 0; j < NC; j++) cp16(base + OBH + dsw[j], pbh + j * 8, bs);\
        if (TERMS == 3) {                                                     \
            const bf16* pbl = bok ? (Bl + kb) : Bl;                           \
            _Pragma("unroll")                                                 \
            for (int j = 0; j < NC; j++) cp16(base + OAL + dsw[j], Al + ka + j * 8, 16);\
            _Pragma("unroll")                                                 \
            for (int j = 0; j < NC; j++) cp16(base + OBL + dsw[j], pbl + j * 8, bs);\
        }                                                                     \
        CP_COMMIT();                                                          \
    } while (0)

    LOAD_STAGE(0);

    for (int s = 0; s < S; s++) {
        if (s + 1 < S) { LOAD_STAGE(s + 1); CP_WAIT(1); }
        else           { CP_WAIT(0); }
        __syncthreads();

        const uint32_t pb = sb + (s & 1) * STG;
#pragma unroll
        for (int kc = 0; kc < BK / 16; kc++) {
            uint32_t ah[4][4], al[4][4];
#pragma unroll
            for (int mt = 0; mt < 4; mt++) {
                uint32_t v = (uint32_t)((arow + mt * 16) * ROWB + kc * 32 + khalf);
                uint32_t off = (ROWB == 128) ? swz128(v) : swz64(v);
                ldsm4(ah[mt], pb + off);
                if (TERMS == 3) ldsm4(al[mt], pb + OAL + off);
            }
#pragma unroll
            for (int np = 0; np < 2; np++) {
                uint32_t v = (uint32_t)((brow + np * 16) * ROWB + kc * 32 + khalf);
                uint32_t boffs = (ROWB == 128) ? swz128(v) : swz64(v);
                uint32_t bh4[4], bl4[4];
                ldsm4(bh4, pb + OBH + boffs);
                if (TERMS == 3) ldsm4(bl4, pb + OBL + boffs);
#pragma unroll
                for (int mt = 0; mt < 4; mt++) {
                    mma16816(acc[mt][np * 2],     ah[mt], bh4[0], bh4[2]);
                    mma16816(acc[mt][np * 2 + 1], ah[mt], bh4[1], bh4[3]);
                    if (TERMS == 3) {
                        mma16816(acc[mt][np * 2],     ah[mt], bl4[0], bl4[2]);
                        mma16816(acc[mt][np * 2],     al[mt], bh4[0], bh4[2]);
                        mma16816(acc[mt][np * 2 + 1], ah[mt], bl4[1], bl4[3]);
                        mma16816(acc[mt][np * 2 + 1], al[mt], bh4[1], bh4[3]);
                    }
                }
            }
        }
        __syncthreads();
    }

    const int gid = lane >> 2, tg = lane & 3;
#pragma unroll
    for (int mt = 0; mt < 4; mt++) {
#pragma unroll
        for (int nt = 0; nt < 4; nt++) {
            int gn = n0 + wn * 32 + nt * 8 + tg * 2;
            if (gn < N) {
                int gm = m0 + wm * 64 + mt * 16 + gid;
                float* cp0 = C + (size_t)gm * N + gn;
                float* cp1 = C + (size_t)(gm + 8) * N + gn;
                float2 v0 = make_float2(acc[mt][nt][0], acc[mt][nt][1]);
                float2 v1 = make_float2(acc[mt][nt][2], acc[mt][nt][3]);
                if (EPI == 1) {
                    float2 o0 = *(const float2*)cp0, o1 = *(const float2*)cp1;
                    v0.x += o0.x; v0.y += o0.y; v1.x += o1.x; v1.y += o1.y;
                } else if (EPI == 2) {
                    float b0 = bias[gn], b1 = bias[gn + 1];
                    v0.x = softplusf(v0.x + b0); v0.y = softplusf(v0.y + b1);
                    v1.x = softplusf(v1.x + b0); v1.y = softplusf(v1.y + b1);
                }
                *(float2*)cp0 = v0;
                *(float2*)cp1 = v1;
            }
        }
    }
#undef LOAD_STAGE
}

// ---------------- 3-phase scan: 16 states per thread ------------------------
// Phase A: per (d, chunk) compute (prod dA, carry) for all 16 states.
// thread = channel d; warp = 32 consecutive d -> coalesced dt/xm loads.
#define LOG2E 1.44269504088896f
__global__ __launch_bounds__(256)
void scanA(const float* __restrict__ dt, const float* __restrict__ xm,
           const float* __restrict__ dbc, const float* __restrict__ A_log,
           float* __restrict__ sa, float* __restrict__ sb)
{
    int d = blockIdx.x * 256 + threadIdx.x;
    int c = blockIdx.y, b = blockIdx.z;
    float A2[16];
#pragma unroll
    for (int s = 0; s < 16; s++)
        A2[s] = -__expf(A_log[d * NS + s]) * LOG2E;
    int m0 = b * SEQ + c * CH;
    const float* dtp = dt + (size_t)m0 * DI + d;
    const float* xmp = xm + (size_t)m0 * DI + d;
    const float* bcp = dbc + (size_t)m0 * 96 + DTR;
    float ap[16], bc_[16];
#pragma unroll
    for (int s = 0; s < 16; s++) { ap[s] = 1.f; bc_[s] = 0.f; }
    for (int l = 0; l < CH; l++) {
        float dtv = dtp[(size_t)l * DI];
        float xv  = xmp[(size_t)l * DI];
        float dtx = dtv * xv;
        float4 B0 = *(const float4*)(bcp + l * 96);
        float4 B1 = *(const float4*)(bcp + l * 96 + 4);
        float4 B2 = *(const float4*)(bcp + l * 96 + 8);
        float4 B3 = *(const float4*)(bcp + l * 96 + 12);
        float Bv[16] = {B0.x,B0.y,B0.z,B0.w, B1.x,B1.y,B1.z,B1.w,
                        B2.x,B2.y,B2.z,B2.w, B3.x,B3.y,B3.z,B3.w};
#pragma unroll
        for (int s = 0; s < 16; s++) {
            float dA = ex2f(dtv * A2[s]);
            ap[s] *= dA;
            bc_[s] = fmaf(dA, bc_[s], dtx * Bv[s]);
        }
    }
    size_t o = ((size_t)(b * NCH + c) * DI + d) * NS;
#pragma unroll
    for (int s = 0; s < 16; s += 4) {
        *(float4*)(sa + o + s) = make_float4(ap[s], ap[s+1], ap[s+2], ap[s+3]);
        *(float4*)(sb + o + s) = make_float4(bc_[s], bc_[s+1], bc_[s+2], bc_[s+3]);
    }
}

// Phase B: serial combine over chunks; thread = (b, d, s).
__global__ __launch_bounds__(256)
void scanB(const float* __restrict__ sa, const float* __restrict__ sb,
           float* __restrict__ hin)
{
    int i = blockIdx.x * 256 + threadIdx.x;     // over BATCH*DI*NS
    int b  = i / (DI * NS);
    int ds = i - b * (DI * NS);
    float h = 0.f;
#pragma unroll 4
    for (int c = 0; c < NCH; c++) {
        size_t o = (size_t)(b * NCH + c) * (DI * NS) + ds;
        float a  = sa[o];
        float bb = sb[o];
        hin[o] = h;
        h = fmaf(a, h, bb);
    }
}

// Phase C: replay chunk from h_init, emit y = (sum_s h*C + x*D) * silu(z).
__global__ __launch_bounds__(256)
void scanC(const float* __restrict__ dt, const float* __restrict__ xm,
           const float* __restrict__ xz, const float* __restrict__ dbc,
           const float* __restrict__ A_log, const float* __restrict__ Dsk,
           const float* __restrict__ hin, bf16* __restrict__ yh)
{
    int d = blockIdx.x * 256 + threadIdx.x;
    int c = blockIdx.y, b = blockIdx.z;
    float A2[16];
#pragma unroll
    for (int s = 0; s < 16; s++)
        A2[s] = -__expf(A_log[d * NS + s]) * LOG2E;
    float Dv = Dsk[d];
    size_t o = ((size_t)(b * NCH + c) * DI + d) * NS;
    float h[16];
#pragma unroll
    for (int s = 0; s < 16; s += 4) {
        float4 hv = *(const float4*)(hin + o + s);
        h[s] = hv.x; h[s+1] = hv.y; h[s+2] = hv.z; h[s+3] = hv.w;
    }
    int m0 = b * SEQ + c * CH;
    const float* dtp = dt + (size_t)m0 * DI + d;
    const float* xmp = xm + (size_t)m0 * DI + d;
    const float* zp  = xz + (size_t)m0 * (2 * DI) + DI + d;
    const float* bcp = dbc + (size_t)m0 * 96 + DTR;
    bf16* yp = yh + (size_t)m0 * DI + d;
    for (int l = 0; l < CH; l++) {
        float dtv = dtp[(size_t)l * DI];
        float xv  = xmp[(size_t)l * DI];
        float zv  = zp[(size_t)l * (2 * DI)];
        float dtx = dtv * xv;
        float4 B0 = *(const float4*)(bcp + l * 96);
        float4 B1 = *(const float4*)(bcp + l * 96 + 4);
        float4 B2 = *(const float4*)(bcp + l * 96 + 8);
        float4 B3 = *(const float4*)(bcp + l * 96 + 12);
        float4 C0 = *(const float4*)(bcp + l * 96 + 16);
        float4 C1 = *(const float4*)(bcp + l * 96 + 20);
        float4 C2 = *(const float4*)(bcp + l * 96 + 24);
        float4 C3 = *(const float4*)(bcp + l * 96 + 28);
        float Bv[16] = {B0.x,B0.y,B0.z,B0.w, B1.x,B1.y,B1.z,B1.w,
                        B2.x,B2.y,B2.z,B2.w, B3.x,B3.y,B3.z,B3.w};
        float Cv[16] = {C0.x,C0.y,C0.z,C0.w, C1.x,C1.y,C1.z,C1.w,
                        C2.x,C2.y,C2.z,C2.w, C3.x,C3.y,C3.z,C3.w};
        float y0 = 0.f, y1 = 0.f, y2 = 0.f, y3 = 0.f;
#pragma unroll
        for (int s = 0; s < 16; s += 4) {
            float dA0 = ex2f(dtv * A2[s]);
            float dA1 = ex2f(dtv * A2[s+1]);
            float dA2 = ex2f(dtv * A2[s+2]);
            float dA3 = ex2f(dtv * A2[s+3]);
            h[s]   = fmaf(dA0, h[s],   dtx * Bv[s]);
            h[s+1] = fmaf(dA1, h[s+1], dtx * Bv[s+1]);
            h[s+2] = fmaf(dA2, h[s+2], dtx * Bv[s+2]);
            h[s+3] = fmaf(dA3, h[s+3], dtx * Bv[s+3]);
            y0 = fmaf(h[s],   Cv[s],   y0);
            y1 = fmaf(h[s+1], Cv[s+1], y1);
            y2 = fmaf(h[s+2], Cv[s+2], y2);
            y3 = fmaf(h[s+3], Cv[s+3], y3);
        }
        float yv = (y0 + y1) + (y2 + y3) + xv * Dv;
        yv *= zv / (1.f + __expf(-zv));
        yp[(size_t)l * DI] = __float2bfloat16(yv);
    }
}

// ---------------- driver ---------------------------------------------------
#define SMEM_G 65536
extern "C" void kernel_launch(void* const* d_in, const int* in_sizes, int n_in,
                              void* d_out, int out_size)
{
    const float* x_in   = (const float*)d_in[0];
    const float* in_w   = (const float*)d_in[1];
    const float* conv_w = (const float*)d_in[2];
    const float* conv_b = (const float*)d_in[3];
    const float* xp_w   = (const float*)d_in[4];
    const float* dt_w   = (const float*)d_in[5];
    const float* dt_b   = (const float*)d_in[6];
    const float* A_log  = (const float*)d_in[7];
    const float* D_sk   = (const float*)d_in[8];
    const float* out_w  = (const float*)d_in[9];
    const float* ln_g   = (const float*)d_in[10];
    const float* ln_b   = (const float*)d_in[11];
    float* out = (float*)d_out;

    float *px, *pxz, *pxm, *pdt, *pdbcp, *pdbc, *psa, *psb, *phin;
    bf16 *plnh, *pxmh, *pxml, *pdbch, *pdbcl, *pyh;
    bf16 *pwinh, *pwxph, *pwxpl, *pwdth, *pwdtl, *pwoh;
    cudaGetSymbolAddress((void**)&px,    g_x);
    cudaGetSymbolAddress((void**)&pxz,   g_xz);
    cudaGetSymbolAddress((void**)&pxm,   g_xm);
    cudaGetSymbolAddress((void**)&pdt,   g_dt);
    cudaGetSymbolAddress((void**)&pdbcp, g_dbcp);
    cudaGetSymbolAddress((void**)&pdbc,  g_dbc);
    cudaGetSymbolAddress((void**)&psa,   g_sa);
    cudaGetSymbolAddress((void**)&psb,   g_sb);
    cudaGetSymbolAddress((void**)&phin,  g_hin);
    cudaGetSymbolAddress((void**)&plnh,  g_lnh);
    cudaGetSymbolAddress((void**)&pxmh,  g_xmh);
    cudaGetSymbolAddress((void**)&pxml,  g_xml);
    cudaGetSymbolAddress((void**)&pdbch, g_dbch);
    cudaGetSymbolAddress((void**)&pdbcl, g_dbcl);
    cudaGetSymbolAddress((void**)&pyh,   g_yh);
    cudaGetSymbolAddress((void**)&pwinh, w_inh);
    cudaGetSymbolAddress((void**)&pwxph, w_xph);
    cudaGetSymbolAddress((void**)&pwxpl, w_xpl);
    cudaGetSymbolAddress((void**)&pwdth, w_dth);
    cudaGetSymbolAddress((void**)&pwdtl, w_dtl);
    cudaGetSymbolAddress((void**)&pwoh,  w_outh);

    cudaFuncSetAttribute(gemmbf<0,1>, cudaFuncAttributeMaxDynamicSharedMemorySize, SMEM_G);
    cudaFuncSetAttribute(gemmbf<1,1>, cudaFuncAttributeMaxDynamicSharedMemorySize, SMEM_G);
    cudaFuncSetAttribute(gemmbf<0,3>, cudaFuncAttributeMaxDynamicSharedMemorySize, SMEM_G);
    cudaFuncSetAttribute(gemmbf<2,3>, cudaFuncAttributeMaxDynamicSharedMemorySize, SMEM_G);

    // launches 1-3
    copy_kernel<<<(MTOT * DM) / 256, 256>>>(x_in, px, MTOT * DM);
    cvt_hi<<<(NL * 2 * DI * DM / 8 + 255) / 256, 256>>>(in_w, pwinh, NL * 2 * DI * DM / 8);
    ln_kernel<1><<<MTOT, 256>>>(px, nullptr, plnh, ln_g, ln_b);
    // launch 4: PROBE scanC (ncu capture slot); deterministic on steady-state
    // buffers, output overwritten by real layer-0 scan.
    scanC<<<dim3(DI / 256, NCH, BATCH), 256>>>(pdt, pxm, pxz, pdbc,
                                               A_log, D_sk, phin, pyh);
    // layer 0 in_proj: xz[MTOT, 2*DI]
    gemmbf<0,1><<<dim3((2 * DI) / 128, MTOT / 128, 1), 256, SMEM_G>>>(
        plnh, plnh, DM, pwinh, pwinh, DM, pxz, MTOT, 2 * DI, DM, nullptr);
    // remaining weight conversions
    cvt_hi<<<(NL * DM * DI / 8 + 255) / 256, 256>>>(out_w, pwoh, NL * DM * DI / 8);
    cvt_split<<<(NL * 96 * DI / 8 + 255) / 256, 256>>>(xp_w, pwxph, pwxpl, NL * 96 * DI / 8);
    cvt_split<<<(NL * DI * DTR / 8 + 255) / 256, 256>>>(dt_w, pwdth, pwdtl, NL * DI * DTR / 8);

    for (int i = 0; i < NL; i++) {
        if (i > 0) {
            ln_kernel<1><<<MTOT, 256>>>(px, nullptr, plnh, ln_g, ln_b);
            gemmbf<0,1><<<dim3((2 * DI) / 128, MTOT / 128, 1), 256, SMEM_G>>>(
                plnh, plnh, DM, pwinh + (size_t)i * 2 * DI * DM,
                pwinh, DM, pxz, MTOT, 2 * DI, DM, nullptr);
        }
        // token-major conv + silu
        conv_silu<<<dim3(DI / 256, SEQ, BATCH), 256>>>(
            pxz, conv_w + (size_t)i * DI * DC, conv_b + (size_t)i * DI,
            pxm, pxmh, pxml);
        // x_proj (token-major out [MTOT,96], 3-term, split-K 8)
        gemmbf<0,3><<<dim3(1, MTOT / 128, KSPLIT), 256, SMEM_G>>>(
            pxmh, pxml, DI,
            pwxph + (size_t)i * 96 * DI, pwxpl + (size_t)i * 96 * DI, DI,
            pdbcp, MTOT, 96, DI / KSPLIT, nullptr);
        reduce8<<<(MTOT * 96) / 256, 256>>>(pdbcp, pdbc, pdbch, pdbcl);
        // dt_proj (token-major out [MTOT, DI]) + col bias + softplus
        gemmbf<2,3><<<dim3(DI / 128, MTOT / 128, 1), 256, SMEM_G>>>(
            pdbch, pdbcl, 96,
            pwdth + (size_t)i * DI * DTR, pwdtl + (size_t)i * DI * DTR, DTR,
            pdt, MTOT, DI, DTR, dt_b + (size_t)i * DI);
        // 3-phase scan
        scanA<<<dim3(DI / 256, NCH, BATCH), 256>>>(
            pdt, pxm, pdbc, A_log + (size_t)i * DI * NS, psa, psb);
        scanB<<<(BATCH * DI * NS) / 256, 256>>>(psa, psb, phin);
        scanC<<<dim3(DI / 256, NCH, BATCH), 256>>>(
            pdt, pxm, pxz, pdbc, A_log + (size_t)i * DI * NS,
            D_sk + (size_t)i * DI, phin, pyh);
        // out_proj accumulated into residual
        gemmbf<1,1><<<dim3(DM / 128, MTOT / 128, 1), 256, SMEM_G>>>(
            pyh, pyh, DI,
            pwoh + (size_t)i * DM * DI, pwoh, DI,
            px, MTOT, DM, DI, nullptr);
    }

    ln_kernel<0><<<MTOT, 256>>>(px, out, nullptr, ln_g, ln_b);
}

// round 13
// speedup vs baseline: 5.1994x; 1.1114x over previous
#include <cuda_runtime.h>
#include <cuda_bf16.h>
#include <cstdint>
#include <math.h>

#define NL    4
#define BATCH 2
#define SEQ   1024
#define DM    1024
#define DI    2048
#define DTR   64
#define NS    16
#define DC    4
#define MTOT  (BATCH*SEQ)   // 2048
#define KSPLIT 8
#define NCH   32            // scan chunks
#define CH    32            // chunk length (NCH*CH = SEQ)

typedef __nv_bfloat16 bf16;

// ---------------- scratch (device globals; no allocation allowed) ----------
__device__ float g_x   [MTOT*DM];
__device__ float g_xz  [MTOT*2*DI];     // token-major
__device__ float g_xm  [MTOT*DI];       // token-major fp32
__device__ float g_dt  [MTOT*DI];       // token-major fp32
__device__ float g_dbcp[KSPLIT*MTOT*96];
__device__ float g_dbc [MTOT*96];
__device__ float g_sa  [BATCH*NCH*DI*NS];   // chunk prod(dA)
__device__ float g_sb  [BATCH*NCH*DI*NS];   // chunk carry
__device__ float g_hin [BATCH*NCH*DI*NS];   // per-chunk initial state

__device__ __align__(128) bf16 g_lnh[MTOT*DM];
__device__ __align__(128) bf16 g_xmh[MTOT*DI];
__device__ __align__(128) bf16 g_xml[MTOT*DI];
__device__ __align__(128) bf16 g_dbch[MTOT*96];
__device__ __align__(128) bf16 g_dbcl[MTOT*96];
__device__ __align__(128) bf16 g_yh [MTOT*DI];
__device__ __align__(128) bf16 w_inh [NL*2*DI*DM];
__device__ __align__(128) bf16 w_xph [NL*96*DI];
__device__ __align__(128) bf16 w_xpl [NL*96*DI];
__device__ __align__(128) bf16 w_dth [NL*DI*DTR];
__device__ __align__(128) bf16 w_dtl [NL*DI*DTR];
__device__ __align__(128) bf16 w_outh[NL*DM*DI];

// ---------------- helpers --------------------------------------------------
__device__ __forceinline__ uint32_t smem_u32(const void* p) {
    uint32_t a;
    asm("{ .reg .u64 t; cvta.to.shared.u64 t, %1; cvt.u32.u64 %0, t; }"
        : "=r"(a) : "l"(p));
    return a;
}
__device__ __forceinline__ uint32_t swz128(uint32_t x) { return x ^ ((x >> 3) & 0x70u); }
__device__ __forceinline__ uint32_t swz64 (uint32_t x) { return x ^ ((x >> 3) & 0x30u); }
__device__ __forceinline__ float ex2f(float x) {
    float r; asm("ex2.approx.ftz.f32 %0, %1;" : "=f"(r) : "f"(x)); return r;
}

__device__ __forceinline__ void cp16(uint32_t dst, const void* src, int sz) {
    asm volatile("cp.async.cg.shared.global [%0], [%1], 16, %2;"
                 :: "r"(dst), "l"(src), "r"(sz) : "memory");
}
#define CP_COMMIT() asm volatile("cp.async.commit_group;" ::: "memory")
#define CP_WAIT(n)  asm volatile("cp.async.wait_group %0;" :: "n"(n) : "memory")

__device__ __forceinline__ void ldsm4(uint32_t* d, uint32_t addr) {
    asm volatile("ldmatrix.sync.aligned.m8n8.x4.shared.b16 {%0,%1,%2,%3}, [%4];"
        : "=r"(d[0]), "=r"(d[1]), "=r"(d[2]), "=r"(d[3]) : "r"(addr));
}
__device__ __forceinline__ void mma16816(float* c, const uint32_t* a,
                                         uint32_t b0, uint32_t b1) {
    asm volatile(
        "mma.sync.aligned.m16n8k16.row.col.f32.bf16.bf16.f32 "
        "{%0,%1,%2,%3}, {%4,%5,%6,%7}, {%8,%9}, {%0,%1,%2,%3};"
        : "+f"(c[0]), "+f"(c[1]), "+f"(c[2]), "+f"(c[3])
        : "r"(a[0]), "r"(a[1]), "r"(a[2]), "r"(a[3]), "r"(b0), "r"(b1));
}

__device__ __forceinline__ float softplusf(float v) {
    return (v > 20.f) ? v : log1pf(__expf(v));
}
__device__ __forceinline__ void split_bf16(float v, bf16* hp, bf16* lp) {
    bf16 h = __float2bfloat16(v);
    *hp = h;
    *lp = __float2bfloat16(v - __bfloat162float(h));
}

// ---------------- misc kernels --------------------------------------------
__global__ void copy_kernel(const float* __restrict__ a, float* __restrict__ o, int n) {
    int i = blockIdx.x * 256 + threadIdx.x;
    if (i < n) o[i] = a[i];
}
__global__ void cvt_hi(const float* __restrict__ src, bf16* __restrict__ hi, int n8) {
    int i = blockIdx.x * 256 + threadIdx.x;
    if (i >= n8) return;
    const float4* s = (const float4*)(src + (size_t)i * 8);
    float4 a = s[0], b = s[1];
    bf16 t[8];
    t[0]=__float2bfloat16(a.x); t[1]=__float2bfloat16(a.y);
    t[2]=__float2bfloat16(a.z); t[3]=__float2bfloat16(a.w);
    t[4]=__float2bfloat16(b.x); t[5]=__float2bfloat16(b.y);
    t[6]=__float2bfloat16(b.z); t[7]=__float2bfloat16(b.w);
    *(uint4*)(hi + (size_t)i * 8) = *(uint4*)t;
}
__global__ void cvt_split(const float* __restrict__ src, bf16* __restrict__ hi,
                          bf16* __restrict__ lo, int n8) {
    int i = blockIdx.x * 256 + threadIdx.x;
    if (i >= n8) return;
    const float4* s = (const float4*)(src + (size_t)i * 8);
    float4 a = s[0], b = s[1];
    float v[8] = {a.x, a.y, a.z, a.w, b.x, b.y, b.z, b.w};
    bf16 th[8], tl[8];
#pragma unroll
    for (int j = 0; j < 8; j++) {
        bf16 h = __float2bfloat16(v[j]);
        th[j] = h;
        tl[j] = __float2bfloat16(v[j] - __bfloat162float(h));
    }
    *(uint4*)(hi + (size_t)i * 8) = *(uint4*)th;
    *(uint4*)(lo + (size_t)i * 8) = *(uint4*)tl;
}

// ---------------- layernorm -------------------------------------------------
template<int BF>
__global__ __launch_bounds__(256)
void ln_kernel(const float* __restrict__ in, float* __restrict__ outp,
               bf16* __restrict__ oh,
               const float* __restrict__ gw, const float* __restrict__ bw)
{
    int row = blockIdx.x;
    int t = threadIdx.x;
    float4 v = ((const float4*)(in + (size_t)row * DM))[t];
    float s  = v.x + v.y + v.z + v.w;
    float s2 = v.x*v.x + v.y*v.y + v.z*v.z + v.w*v.w;
#pragma unroll
    for (int o = 16; o > 0; o >>= 1) {
        s  += __shfl_xor_sync(0xffffffffu, s,  o);
        s2 += __shfl_xor_sync(0xffffffffu, s2, o);
    }
    __shared__ float sh[16];
    if ((t & 31) == 0) { sh[t >> 5] = s; sh[(t >> 5) + 8] = s2; }
    __syncthreads();
    float S = 0.f, S2 = 0.f;
#pragma unroll
    for (int i = 0; i < 8; i++) { S += sh[i]; S2 += sh[i + 8]; }
    float mu  = S * (1.f / DM);
    float var = S2 * (1.f / DM) - mu * mu;
    float r   = rsqrtf(var + 1e-5f);
    float4 g = ((const float4*)gw)[t];
    float4 b = ((const float4*)bw)[t];
    float4 o4;
    o4.x = (v.x - mu) * r * g.x + b.x;
    o4.y = (v.y - mu) * r * g.y + b.y;
    o4.z = (v.z - mu) * r * g.z + b.z;
    o4.w = (v.w - mu) * r * g.w + b.w;
    if (BF) {
        bf16 t4[4] = {__float2bfloat16(o4.x), __float2bfloat16(o4.y),
                      __float2bfloat16(o4.z), __float2bfloat16(o4.w)};
        *(uint2*)(oh + (size_t)row * DM + t * 4) = *(uint2*)t4;
    } else {
        ((float4*)(outp + (size_t)row * DM))[t] = o4;
    }
}

// ---------------- token-major causal conv (k=4) + SiLU + bf16 split --------
__global__ __launch_bounds__(256)
void conv_silu(const float* __restrict__ xz, const float* __restrict__ cw,
               const float* __restrict__ cb, float* __restrict__ xmout,
               bf16* __restrict__ oh, bf16* __restrict__ ol)
{
    int d = blockIdx.x * 256 + threadIdx.x;
    int l = blockIdx.y;
    int b = blockIdx.z;
    float acc = cb[d];
#pragma unroll
    for (int j = 0; j < DC; j++) {
        int lj = l - (DC - 1) + j;
        if (lj >= 0)
            acc = fmaf(cw[d * DC + j], xz[(size_t)(b * SEQ + lj) * (2 * DI) + d], acc);
    }
    float sv = acc / (1.f + __expf(-acc));
    size_t o = (size_t)(b * SEQ + l) * DI + d;
    xmout[o] = sv;
    split_bf16(sv, oh + o, ol + o);
}

// ---------------- reduce split-K partials + bf16 split --------------------
__global__ void reduce8(const float* __restrict__ part, float* __restrict__ outp,
                        bf16* __restrict__ oh, bf16* __restrict__ ol)
{
    int i = blockIdx.x * 256 + threadIdx.x;
    float s = 0.f;
#pragma unroll
    for (int k = 0; k < KSPLIT; k++) s += part[(size_t)k * (MTOT * 96) + i];
    outp[i] = s;
    split_bf16(s, oh + i, ol + i);
}

// ---------------- bf16 GEMM, cp.async double-buffered ----------------------
template<int EPI, int TERMS>
__global__ __launch_bounds__(256, 2)
void gemmbf(const bf16* __restrict__ Ah, const bf16* __restrict__ Al, int lda,
            const bf16* __restrict__ Bh, const bf16* __restrict__ Bl, int ldb,
            float* __restrict__ C, int M, int N, int K,
            const float* __restrict__ bias)
{
    constexpr int BK   = (TERMS == 1) ? 64 : 32;
    constexpr int ROWB = BK * 2;
    constexpr int NC   = BK / 16;
    constexpr uint32_t OAL = 8192;
    constexpr uint32_t OBH = 16384;
    constexpr uint32_t OBL = 24576;
    constexpr uint32_t STG = 32768;

    extern __shared__ char smem[];
    const uint32_t sb = smem_u32(smem);
    const int tid = threadIdx.x, wid = tid >> 5, lane = tid & 31;
    const int m0 = blockIdx.y * 128, n0 = blockIdx.x * 128;
    const long kbeg = (long)blockIdx.z * K;
    if (gridDim.z > 1) C += (size_t)blockIdx.z * M * N;

    const int wm = wid >> 2, wn = wid & 3;

    const int r = tid >> 1, hh = tid & 1;
    const int helems = hh * (BK / 2);
    const size_t arow_g = (size_t)(m0 + r) * lda + kbeg + helems;
    const size_t brow_g = (size_t)(n0 + r) * ldb + kbeg + helems;
    const bool bok = (n0 + r) < N;
    uint32_t dsw[NC];
#pragma unroll
    for (int j = 0; j < NC; j++) {
        uint32_t v = (uint32_t)(r * ROWB + hh * (ROWB / 2) + j * 16);
        dsw[j] = (ROWB == 128) ? swz128(v) : swz64(v);
    }

    const int g = lane >> 3, r8 = lane & 7;
    const int arow = wm * 64 + (g & 1) * 8 + r8;
    const int brow = wn * 32 + (g & 1) * 8 + r8;
    const int khalf = (g >> 1) * 16;

    float acc[4][4][4];
#pragma unroll
    for (int i = 0; i < 4; i++)
#pragma unroll
        for (int j = 0; j < 4; j++)
#pragma unroll
            for (int q = 0; q < 4; q++) acc[i][j][q] = 0.f;

    const int S = K / BK;

#define LOAD_STAGE(s)  do {                                                   \
        uint32_t base = sb + ((s) & 1) * STG;                                 \
        size_t ka = arow_g + (size_t)(s) * BK;                                \
        size_t kb = brow_g + (size_t)(s) * BK;                                \
        const bf16* pbh = bok ? (Bh + kb) : Bh;                               \
        int bs = bok ? 16 : 0;                                                \
        _Pragma("unroll")                                                     \
        for (int j = 0; j < NC; j++) cp16(base + dsw[j], Ah + ka + j * 8, 16);\
        _Pragma("unroll")                                                     \
        for (int j = 0; j < NC; j++) cp16(base + OBH + dsw[j], pbh + j * 8, bs);\
        if (TERMS == 3) {                                                     \
            const bf16* pbl = bok ? (Bl + kb) : Bl;                           \
            _Pragma("unroll")                                                 \
            for (int j = 0; j < NC; j++) cp16(base + OAL + dsw[j], Al + ka + j * 8, 16);\
            _Pragma("unroll")                                                 \
            for (int j = 0; j < NC; j++) cp16(base + OBL + dsw[j], pbl + j * 8, bs);\
        }                                                                     \
        CP_COMMIT();                                                          \
    } while (0)

    LOAD_STAGE(0);

    for (int s = 0; s < S; s++) {
        if (s + 1 < S) { LOAD_STAGE(s + 1); CP_WAIT(1); }
        else           { CP_WAIT(0); }
        __syncthreads();

        const uint32_t pb = sb + (s & 1) * STG;
#pragma unroll
        for (int kc = 0; kc < BK / 16; kc++) {
            uint32_t ah[4][4], al[4][4];
#pragma unroll
            for (int mt = 0; mt < 4; mt++) {
                uint32_t v = (uint32_t)((arow + mt * 16) * ROWB + kc * 32 + khalf);
                uint32_t off = (ROWB == 128) ? swz128(v) : swz64(v);
                ldsm4(ah[mt], pb + off);
                if (TERMS == 3) ldsm4(al[mt], pb + OAL + off);
            }
#pragma unroll
            for (int np = 0; np < 2; np++) {
                uint32_t v = (uint32_t)((brow + np * 16) * ROWB + kc * 32 + khalf);
                uint32_t boffs = (ROWB == 128) ? swz128(v) : swz64(v);
                uint32_t bh4[4], bl4[4];
                ldsm4(bh4, pb + OBH + boffs);
                if (TERMS == 3) ldsm4(bl4, pb + OBL + boffs);
#pragma unroll
                for (int mt = 0; mt < 4; mt++) {
                    mma16816(acc[mt][np * 2],     ah[mt], bh4[0], bh4[2]);
                    mma16816(acc[mt][np * 2 + 1], ah[mt], bh4[1], bh4[3]);
                    if (TERMS == 3) {
                        mma16816(acc[mt][np * 2],     ah[mt], bl4[0], bl4[2]);
                        mma16816(acc[mt][np * 2],     al[mt], bh4[0], bh4[2]);
                        mma16816(acc[mt][np * 2 + 1], ah[mt], bl4[1], bl4[3]);
                        mma16816(acc[mt][np * 2 + 1], al[mt], bh4[1], bh4[3]);
                    }
                }
            }
        }
        __syncthreads();
    }

    const int gid = lane >> 2, tg = lane & 3;
#pragma unroll
    for (int mt = 0; mt < 4; mt++) {
#pragma unroll
        for (int nt = 0; nt < 4; nt++) {
            int gn = n0 + wn * 32 + nt * 8 + tg * 2;
            if (gn < N) {
                int gm = m0 + wm * 64 + mt * 16 + gid;
                float* cp0 = C + (size_t)gm * N + gn;
                float* cp1 = C + (size_t)(gm + 8) * N + gn;
                float2 v0 = make_float2(acc[mt][nt][0], acc[mt][nt][1]);
                float2 v1 = make_float2(acc[mt][nt][2], acc[mt][nt][3]);
                if (EPI == 1) {
                    float2 o0 = *(const float2*)cp0, o1 = *(const float2*)cp1;
                    v0.x += o0.x; v0.y += o0.y; v1.x += o1.x; v1.y += o1.y;
                } else if (EPI == 2) {
                    float b0 = bias[gn], b1 = bias[gn + 1];
                    v0.x = softplusf(v0.x + b0); v0.y = softplusf(v0.y + b1);
                    v1.x = softplusf(v1.x + b0); v1.y = softplusf(v1.y + b1);
                }
                *(float2*)cp0 = v0;
                *(float2*)cp1 = v1;
            }
        }
    }
#undef LOAD_STAGE
}

// ---------------- 3-phase scan: 16 states per thread, prefetched ------------
#define LOG2E 1.44269504088896f
__global__ __launch_bounds__(256)
void scanA(const float* __restrict__ dt, const float* __restrict__ xm,
           const float* __restrict__ dbc, const float* __restrict__ A_log,
           float* __restrict__ sa, float* __restrict__ sb)
{
    int d = blockIdx.x * 256 + threadIdx.x;
    int c = blockIdx.y, b = blockIdx.z;
    float A2[16];
#pragma unroll
    for (int s = 0; s < 16; s++)
        A2[s] = -__expf(A_log[d * NS + s]) * LOG2E;
    int m0 = b * SEQ + c * CH;
    const float* dtp = dt + (size_t)m0 * DI + d;
    const float* xmp = xm + (size_t)m0 * DI + d;
    const float* bcp = dbc + (size_t)m0 * 96 + DTR;
    float ap[16], bc_[16];
#pragma unroll
    for (int s = 0; s < 16; s++) { ap[s] = 1.f; bc_[s] = 0.f; }

    // 2-deep rotating prefetch of the strided scalars
    float dtv = dtp[0], xv = xmp[0];
#pragma unroll 2
    for (int l = 0; l < CH; l++) {
        float dtn = 0.f, xn = 0.f;
        if (l + 1 < CH) {
            dtn = dtp[(size_t)(l + 1) * DI];
            xn  = xmp[(size_t)(l + 1) * DI];
        }
        float dtx = dtv * xv;
        float4 B0 = *(const float4*)(bcp + l * 96);
        float4 B1 = *(const float4*)(bcp + l * 96 + 4);
        float4 B2 = *(const float4*)(bcp + l * 96 + 8);
        float4 B3 = *(const float4*)(bcp + l * 96 + 12);
        float Bv[16] = {B0.x,B0.y,B0.z,B0.w, B1.x,B1.y,B1.z,B1.w,
                        B2.x,B2.y,B2.z,B2.w, B3.x,B3.y,B3.z,B3.w};
#pragma unroll
        for (int s = 0; s < 16; s++) {
            float dA = ex2f(dtv * A2[s]);
            ap[s] *= dA;
            bc_[s] = fmaf(dA, bc_[s], dtx * Bv[s]);
        }
        dtv = dtn; xv = xn;
    }
    size_t o = ((size_t)(b * NCH + c) * DI + d) * NS;
#pragma unroll
    for (int s = 0; s < 16; s += 4) {
        *(float4*)(sa + o + s) = make_float4(ap[s], ap[s+1], ap[s+2], ap[s+3]);
        *(float4*)(sb + o + s) = make_float4(bc_[s], bc_[s+1], bc_[s+2], bc_[s+3]);
    }
}

__global__ __launch_bounds__(256)
void scanB(const float* __restrict__ sa, const float* __restrict__ sb,
           float* __restrict__ hin)
{
    int i = blockIdx.x * 256 + threadIdx.x;     // over BATCH*DI*NS
    int b  = i / (DI * NS);
    int ds = i - b * (DI * NS);
    float h = 0.f;
#pragma unroll 8
    for (int c = 0; c < NCH; c++) {
        size_t o = (size_t)(b * NCH + c) * (DI * NS) + ds;
        float a  = sa[o];
        float bb = sb[o];
        hin[o] = h;
        h = fmaf(a, h, bb);
    }
}

__global__ __launch_bounds__(256)
void scanC(const float* __restrict__ dt, const float* __restrict__ xm,
           const float* __restrict__ xz, const float* __restrict__ dbc,
           const float* __restrict__ A_log, const float* __restrict__ Dsk,
           const float* __restrict__ hin, bf16* __restrict__ yh)
{
    int d = blockIdx.x * 256 + threadIdx.x;
    int c = blockIdx.y, b = blockIdx.z;
    float A2[16];
#pragma unroll
    for (int s = 0; s < 16; s++)
        A2[s] = -__expf(A_log[d * NS + s]) * LOG2E;
    float Dv = Dsk[d];
    size_t o = ((size_t)(b * NCH + c) * DI + d) * NS;
    float h[16];
#pragma unroll
    for (int s = 0; s < 16; s += 4) {
        float4 hv = *(const float4*)(hin + o + s);
        h[s] = hv.x; h[s+1] = hv.y; h[s+2] = hv.z; h[s+3] = hv.w;
    }
    int m0 = b * SEQ + c * CH;
    const float* dtp = dt + (size_t)m0 * DI + d;
    const float* xmp = xm + (size_t)m0 * DI + d;
    const float* zp  = xz + (size_t)m0 * (2 * DI) + DI + d;
    const float* bcp = dbc + (size_t)m0 * 96 + DTR;
    bf16* yp = yh + (size_t)m0 * DI + d;

    float dtv = dtp[0], xv = xmp[0], zv = zp[0];
#pragma unroll 2
    for (int l = 0; l < CH; l++) {
        float dtn = 0.f, xn = 0.f, zn = 0.f;
        if (l + 1 < CH) {
            dtn = dtp[(size_t)(l + 1) * DI];
            xn  = xmp[(size_t)(l + 1) * DI];
            zn  = zp[(size_t)(l + 1) * (2 * DI)];
        }
        float dtx = dtv * xv;
        float4 B0 = *(const float4*)(bcp + l * 96);
        float4 B1 = *(const float4*)(bcp + l * 96 + 4);
        float4 B2 = *(const float4*)(bcp + l * 96 + 8);
        float4 B3 = *(const float4*)(bcp + l * 96 + 12);
        float4 C0 = *(const float4*)(bcp + l * 96 + 16);
        float4 C1 = *(const float4*)(bcp + l * 96 + 20);
        float4 C2 = *(const float4*)(bcp + l * 96 + 24);
        float4 C3 = *(const float4*)(bcp + l * 96 + 28);
        float Bv[16] = {B0.x,B0.y,B0.z,B0.w, B1.x,B1.y,B1.z,B1.w,
                        B2.x,B2.y,B2.z,B2.w, B3.x,B3.y,B3.z,B3.w};
        float Cv[16] = {C0.x,C0.y,C0.z,C0.w, C1.x,C1.y,C1.z,C1.w,
                        C2.x,C2.y,C2.z,C2.w, C3.x,C3.y,C3.z,C3.w};
        float y0 = 0.f, y1 = 0.f, y2 = 0.f, y3 = 0.f;
#pragma unroll
        for (int s = 0; s < 16; s += 4) {
            float dA0 = ex2f(dtv * A2[s]);
            float dA1 = ex2f(dtv * A2[s+1]);
            float dA2 = ex2f(dtv * A2[s+2]);
            float dA3 = ex2f(dtv * A2[s+3]);
            h[s]   = fmaf(dA0, h[s],   dtx * Bv[s]);
            h[s+1] = fmaf(dA1, h[s+1], dtx * Bv[s+1]);
            h[s+2] = fmaf(dA2, h[s+2], dtx * Bv[s+2]);
            h[s+3] = fmaf(dA3, h[s+3], dtx * Bv[s+3]);
            y0 = fmaf(h[s],   Cv[s],   y0);
            y1 = fmaf(h[s+1], Cv[s+1], y1);
            y2 = fmaf(h[s+2], Cv[s+2], y2);
            y3 = fmaf(h[s+3], Cv[s+3], y3);
        }
        float yv = (y0 + y1) + (y2 + y3) + xv * Dv;
        yv *= zv / (1.f + __expf(-zv));
        yp[(size_t)l * DI] = __float2bfloat16(yv);
        dtv = dtn; xv = xn; zv = zn;
    }
}

// ---------------- driver ---------------------------------------------------
#define SMEM_G 65536
extern "C" void kernel_launch(void* const* d_in, const int* in_sizes, int n_in,
                              void* d_out, int out_size)
{
    const float* x_in   = (const float*)d_in[0];
    const float* in_w   = (const float*)d_in[1];
    const float* conv_w = (const float*)d_in[2];
    const float* conv_b = (const float*)d_in[3];
    const float* xp_w   = (const float*)d_in[4];
    const float* dt_w   = (const float*)d_in[5];
    const float* dt_b   = (const float*)d_in[6];
    const float* A_log  = (const float*)d_in[7];
    const float* D_sk   = (const float*)d_in[8];
    const float* out_w  = (const float*)d_in[9];
    const float* ln_g   = (const float*)d_in[10];
    const float* ln_b   = (const float*)d_in[11];
    float* out = (float*)d_out;

    float *px, *pxz, *pxm, *pdt, *pdbcp, *pdbc, *psa, *psb, *phin;
    bf16 *plnh, *pxmh, *pxml, *pdbch, *pdbcl, *pyh;
    bf16 *pwinh, *pwxph, *pwxpl, *pwdth, *pwdtl, *pwoh;
    cudaGetSymbolAddress((void**)&px,    g_x);
    cudaGetSymbolAddress((void**)&pxz,   g_xz);
    cudaGetSymbolAddress((void**)&pxm,   g_xm);
    cudaGetSymbolAddress((void**)&pdt,   g_dt);
    cudaGetSymbolAddress((void**)&pdbcp, g_dbcp);
    cudaGetSymbolAddress((void**)&pdbc,  g_dbc);
    cudaGetSymbolAddress((void**)&psa,   g_sa);
    cudaGetSymbolAddress((void**)&psb,   g_sb);
    cudaGetSymbolAddress((void**)&phin,  g_hin);
    cudaGetSymbolAddress((void**)&plnh,  g_lnh);
    cudaGetSymbolAddress((void**)&pxmh,  g_xmh);
    cudaGetSymbolAddress((void**)&pxml,  g_xml);
    cudaGetSymbolAddress((void**)&pdbch, g_dbch);
    cudaGetSymbolAddress((void**)&pdbcl, g_dbcl);
    cudaGetSymbolAddress((void**)&pyh,   g_yh);
    cudaGetSymbolAddress((void**)&pwinh, w_inh);
    cudaGetSymbolAddress((void**)&pwxph, w_xph);
    cudaGetSymbolAddress((void**)&pwxpl, w_xpl);
    cudaGetSymbolAddress((void**)&pwdth, w_dth);
    cudaGetSymbolAddress((void**)&pwdtl, w_dtl);
    cudaGetSymbolAddress((void**)&pwoh,  w_outh);

    cudaFuncSetAttribute(gemmbf<0,1>, cudaFuncAttributeMaxDynamicSharedMemorySize, SMEM_G);
    cudaFuncSetAttribute(gemmbf<1,1>, cudaFuncAttributeMaxDynamicSharedMemorySize, SMEM_G);
    cudaFuncSetAttribute(gemmbf<0,3>, cudaFuncAttributeMaxDynamicSharedMemorySize, SMEM_G);
    cudaFuncSetAttribute(gemmbf<2,3>, cudaFuncAttributeMaxDynamicSharedMemorySize, SMEM_G);

    // launches 1-3; launch 4 = in_proj GEMM (ncu capture slot)
    copy_kernel<<<(MTOT * DM) / 256, 256>>>(x_in, px, MTOT * DM);
    cvt_hi<<<(NL * 2 * DI * DM / 8 + 255) / 256, 256>>>(in_w, pwinh, NL * 2 * DI * DM / 8);
    ln_kernel<1><<<MTOT, 256>>>(px, nullptr, plnh, ln_g, ln_b);
    gemmbf<0,1><<<dim3((2 * DI) / 128, MTOT / 128, 1), 256, SMEM_G>>>(
        plnh, plnh, DM, pwinh, pwinh, DM, pxz, MTOT, 2 * DI, DM, nullptr);
    // remaining weight conversions
    cvt_hi<<<(NL * DM * DI / 8 + 255) / 256, 256>>>(out_w, pwoh, NL * DM * DI / 8);
    cvt_split<<<(NL * 96 * DI / 8 + 255) / 256, 256>>>(xp_w, pwxph, pwxpl, NL * 96 * DI / 8);
    cvt_split<<<(NL * DI * DTR / 8 + 255) / 256, 256>>>(dt_w, pwdth, pwdtl, NL * DI * DTR / 8);

    for (int i = 0; i < NL; i++) {
        if (i > 0) {
            ln_kernel<1><<<MTOT, 256>>>(px, nullptr, plnh, ln_g, ln_b);
            gemmbf<0,1><<<dim3((2 * DI) / 128, MTOT / 128, 1), 256, SMEM_G>>>(
                plnh, plnh, DM, pwinh + (size_t)i * 2 * DI * DM,
                pwinh, DM, pxz, MTOT, 2 * DI, DM, nullptr);
        }
        conv_silu<<<dim3(DI / 256, SEQ, BATCH), 256>>>(
            pxz, conv_w + (size_t)i * DI * DC, conv_b + (size_t)i * DI,
            pxm, pxmh, pxml);
        gemmbf<0,3><<<dim3(1, MTOT / 128, KSPLIT), 256, SMEM_G>>>(
            pxmh, pxml, DI,
            pwxph + (size_t)i * 96 * DI, pwxpl + (size_t)i * 96 * DI, DI,
            pdbcp, MTOT, 96, DI / KSPLIT, nullptr);
        reduce8<<<(MTOT * 96) / 256, 256>>>(pdbcp, pdbc, pdbch, pdbcl);
        gemmbf<2,3><<<dim3(DI / 128, MTOT / 128, 1), 256, SMEM_G>>>(
            pdbch, pdbcl, 96,
            pwdth + (size_t)i * DI * DTR, pwdtl + (size_t)i * DI * DTR, DTR,
            pdt, MTOT, DI, DTR, dt_b + (size_t)i * DI);
        scanA<<<dim3(DI / 256, NCH, BATCH), 256>>>(
            pdt, pxm, pdbc, A_log + (size_t)i * DI * NS, psa, psb);
        scanB<<<(BATCH * DI * NS) / 256, 256>>>(psa, psb, phin);
        scanC<<<dim3(DI / 256, NCH, BATCH), 256>>>(
            pdt, pxm, pxz, pdbc, A_log + (size_t)i * DI * NS,
            D_sk + (size_t)i * DI, phin, pyh);
        gemmbf<1,1><<<dim3(DM / 128, MTOT / 128, 1), 256, SMEM_G>>>(
            pyh, pyh, DI,
            pwoh + (size_t)i * DM * DI, pwoh, DI,
            px, MTOT, DM, DI, nullptr);
    }

    ln_kernel<0><<<MTOT, 256>>>(px, out, nullptr, ln_g, ln_b);
}